// round 1
// baseline (speedup 1.0000x reference)
#include <cuda_runtime.h>
#include <cuda_bf16.h>

#define BATCH 4
#define CDIM 128
#define FDIM 128
#define TDIM 512
#define HDIM 256
#define MDIM (FDIM*TDIM)   /* 65536 positions per batch */
#define EPSV 1e-6f

// ---------------- scratch (static device globals; no runtime alloc) ----------
__device__ __nv_bfloat16 g_Y[(size_t)BATCH * MDIM * CDIM];   //  64 MB  [b][m][c]
__device__ __nv_bfloat16 g_U[(size_t)BATCH * MDIM * HDIM];   // 128 MB  [b][m][h]
__device__ __nv_bfloat16 g_V[(size_t)BATCH * MDIM * HDIM];   // 128 MB  [b][m][h]
__device__ __nv_bfloat16 g_W1[2 * HDIM * CDIM];              // w_in * g_norm (bf16)
__device__ __nv_bfloat16 g_W2[CDIM * HDIM];                  // w_out (bf16)

// ---------------- kernel 0: weight prep --------------------------------------
__global__ void k_prep(const float* __restrict__ w_in,
                       const float* __restrict__ gn,
                       const float* __restrict__ w_out) {
    int i = blockIdx.x * 256 + threadIdx.x;
    if (i < 2 * HDIM * CDIM)
        g_W1[i] = __float2bfloat16(w_in[i] * gn[i & (CDIM - 1)]);
    if (i < CDIM * HDIM)
        g_W2[i] = __float2bfloat16(w_out[i]);
}

// ---------------- kernel 1: RMSNorm + transpose to [m][c] bf16 ---------------
__global__ __launch_bounds__(256) void k_rms(const float* __restrict__ x,
                                             const float* __restrict__ gn) {
    __shared__ float xs[CDIM][65];   // [c][t] padded
    __shared__ float ps[4][64];
    __shared__ float ssc[64];
    __shared__ float gs[CDIM];
    int b = blockIdx.z, f = blockIdx.y, t0 = blockIdx.x * 64;
    int tid = threadIdx.x;
    const float* xb = x + ((size_t)(b * CDIM) * FDIM + f) * TDIM + t0;
    for (int i = tid; i < CDIM * 64; i += 256) {
        int c = i >> 6, t = i & 63;
        xs[c][t] = xb[(size_t)c * FDIM * TDIM + t];
    }
    if (tid < CDIM) gs[tid] = gn[tid];
    __syncthreads();
    {
        int t = tid & 63, cs = (tid >> 6) * 32;
        float s = 0.f;
#pragma unroll
        for (int c = 0; c < 32; c++) { float v = xs[cs + c][t]; s += v * v; }
        ps[tid >> 6][t] = s;
    }
    __syncthreads();
    if (tid < 64) {
        float s = ps[0][tid] + ps[1][tid] + ps[2][tid] + ps[3][tid];
        ssc[tid] = rsqrtf(s * (1.0f / CDIM) + EPSV);
    }
    __syncthreads();
    __nv_bfloat16* yb = g_Y + ((size_t)b * MDIM + (size_t)f * TDIM + t0) * CDIM;
    for (int i = tid; i < 64 * CDIM; i += 256) {
        int t = i >> 7, c = i & 127;
        yb[(size_t)t * CDIM + c] = __float2bfloat16(xs[c][t] * ssc[t] * gs[c]);
    }
}

// ---------------- mma.sync helper (bf16 m16n8k16, fp32 accum) ----------------
__device__ __forceinline__ void mma16816(float* d, const unsigned* a, const unsigned* bb) {
    asm volatile(
        "mma.sync.aligned.m16n8k16.row.col.f32.bf16.bf16.f32 "
        "{%0,%1,%2,%3},{%4,%5,%6,%7},{%8,%9},{%0,%1,%2,%3};\n"
        : "+f"(d[0]), "+f"(d[1]), "+f"(d[2]), "+f"(d[3])
        : "r"(a[0]), "r"(a[1]), "r"(a[2]), "r"(a[3]), "r"(bb[0]), "r"(bb[1]));
}

// ---------------- kernel 2: GEMM1 (512x128 weights) + bias + GLU -------------
// Block: 128 m-positions x 64 h, full K=128 in smem. 8 warps (4 m x 2 n).
#define S1 136   // smem row stride (elems), 136*2B = 272B (16B aligned, pad kills conflicts)
__global__ __launch_bounds__(256) void k_gemm1(const float* __restrict__ b_in) {
    extern __shared__ __nv_bfloat16 sm1[];
    __nv_bfloat16* As  = sm1;                 // [128][S1]  Y tile  [m][k]
    __nv_bfloat16* Was = sm1 + 128 * S1;      // [64][S1]   Wa rows [h][k]
    __nv_bfloat16* Wbs = Was + 64 * S1;       // [64][S1]   Wb rows
    int b = blockIdx.z;
    int h0 = blockIdx.y * 64;
    size_t m0 = (size_t)blockIdx.x * 128;
    int tid = threadIdx.x;

    const uint4* ysrc = (const uint4*)(g_Y + ((size_t)b * MDIM + m0) * CDIM);
    for (int i = tid; i < 128 * 16; i += 256) {      // 16 uint4 per 128-elem row
        int m = i >> 4, q = i & 15;
        *((uint4*)(As + m * S1) + q) = ysrc[m * 16 + q];
    }
    const uint4* wa = (const uint4*)(g_W1 + h0 * CDIM);
    const uint4* wb = (const uint4*)(g_W1 + (HDIM + h0) * CDIM);
    for (int i = tid; i < 64 * 16; i += 256) {
        int hh = i >> 4, q = i & 15;
        *((uint4*)(Was + hh * S1) + q) = wa[hh * 16 + q];
        *((uint4*)(Wbs + hh * S1) + q) = wb[hh * 16 + q];
    }
    __syncthreads();

    int wid = tid >> 5, lane = tid & 31;
    int wm = wid & 3, wn = wid >> 2;          // m offset wm*32, n offset wn*32
    int gid = lane >> 2, tg = lane & 3;

    float accA[2][4][4], accB[2][4][4];
#pragma unroll
    for (int i = 0; i < 2; i++)
#pragma unroll
        for (int j = 0; j < 4; j++)
#pragma unroll
            for (int r = 0; r < 4; r++) { accA[i][j][r] = 0.f; accB[i][j][r] = 0.f; }

#pragma unroll
    for (int kk = 0; kk < 128; kk += 16) {
        unsigned afr[2][4];
#pragma unroll
        for (int mt = 0; mt < 2; mt++) {
            const __nv_bfloat16* p = As + (wm * 32 + mt * 16 + gid) * S1 + kk + tg * 2;
            afr[mt][0] = *(const unsigned*)p;
            afr[mt][1] = *(const unsigned*)(p + 8 * S1);
            afr[mt][2] = *(const unsigned*)(p + 8);
            afr[mt][3] = *(const unsigned*)(p + 8 * S1 + 8);
        }
#pragma unroll
        for (int nt = 0; nt < 4; nt++) {
            int hr = wn * 32 + nt * 8 + gid;
            const __nv_bfloat16* pa = Was + hr * S1 + kk + tg * 2;
            unsigned bA[2] = { *(const unsigned*)pa, *(const unsigned*)(pa + 8) };
            const __nv_bfloat16* pb = Wbs + hr * S1 + kk + tg * 2;
            unsigned bB[2] = { *(const unsigned*)pb, *(const unsigned*)(pb + 8) };
#pragma unroll
            for (int mt = 0; mt < 2; mt++) {
                mma16816(accA[mt][nt], afr[mt], bA);
                mma16816(accB[mt][nt], afr[mt], bB);
            }
        }
    }

    // epilogue: bias + GLU, write bf16 pairs to g_U[b][m][h]
#pragma unroll
    for (int mt = 0; mt < 2; mt++) {
#pragma unroll
        for (int nt = 0; nt < 4; nt++) {
            int hg = h0 + wn * 32 + nt * 8 + tg * 2;
            float bi0 = b_in[hg],        bi1 = b_in[hg + 1];
            float bg0 = b_in[HDIM + hg], bg1 = b_in[HDIM + hg + 1];
#pragma unroll
            for (int r = 0; r < 2; r++) {
                size_t m = m0 + wm * 32 + mt * 16 + gid + r * 8;
                float a0 = accA[mt][nt][r * 2 + 0] + bi0;
                float a1 = accA[mt][nt][r * 2 + 1] + bi1;
                float g0 = accB[mt][nt][r * 2 + 0] + bg0;
                float g1 = accB[mt][nt][r * 2 + 1] + bg1;
                float u0 = a0 / (1.f + __expf(-g0));
                float u1 = a1 / (1.f + __expf(-g1));
                *(__nv_bfloat162*)(g_U + ((size_t)b * MDIM + m) * HDIM + hg) =
                    __floats2bfloat162_rn(u0, u1);
            }
        }
    }
}

// ---------------- kernel 3: depthwise 3x3 (F same-pad, T causal) + SiLU ------
__global__ __launch_bounds__(256) void k_dw(const float* __restrict__ w_dw,
                                            const float* __restrict__ b_dw) {
    int h = threadIdx.x;                        // 0..255
    int b = blockIdx.z, f = blockIdx.y, t0 = blockIdx.x * 128;
    float wd[9];
#pragma unroll
    for (int i = 0; i < 9; i++) wd[i] = w_dw[h * 9 + i];
    float bd = b_dw[h];
    bool fm = (f > 0), fp = (f < FDIM - 1);
    const __nv_bfloat16* base = g_U + (size_t)b * MDIM * HDIM + h;
    size_t rowm = fm ? (size_t)(f - 1) * TDIM * HDIM : 0;
    size_t row0 = (size_t)f * TDIM * HDIM;
    size_t rowp = fp ? (size_t)(f + 1) * TDIM * HDIM : 0;

    float w0[3] = {0, 0, 0}, w1[3] = {0, 0, 0};  // t-2, t-1 windows per f-row
#pragma unroll
    for (int j = 0; j < 2; j++) {
        int t = t0 - 2 + j;
        if (t >= 0) {
            float vm = fm ? __bfloat162float(base[rowm + (size_t)t * HDIM]) : 0.f;
            float v0 = __bfloat162float(base[row0 + (size_t)t * HDIM]);
            float vp = fp ? __bfloat162float(base[rowp + (size_t)t * HDIM]) : 0.f;
            if (j == 0) { w0[0] = vm; w0[1] = v0; w0[2] = vp; }
            else        { w1[0] = vm; w1[1] = v0; w1[2] = vp; }
        }
    }
    __nv_bfloat16* vout = g_V + ((size_t)b * MDIM + (size_t)f * TDIM + t0) * HDIM + h;
    for (int t = t0; t < t0 + 128; t++) {
        float cm = fm ? __bfloat162float(base[rowm + (size_t)t * HDIM]) : 0.f;
        float c0 = __bfloat162float(base[row0 + (size_t)t * HDIM]);
        float cp = fp ? __bfloat162float(base[rowp + (size_t)t * HDIM]) : 0.f;
        float acc = w0[0] * wd[0] + w1[0] * wd[1] + cm * wd[2]
                  + w0[1] * wd[3] + w1[1] * wd[4] + c0 * wd[5]
                  + w0[2] * wd[6] + w1[2] * wd[7] + cp * wd[8];
        acc += bd;
        *vout = __float2bfloat16(acc / (1.f + __expf(-acc)));
        vout += HDIM;
        w0[0] = w1[0]; w0[1] = w1[1]; w0[2] = w1[2];
        w1[0] = cm;    w1[1] = c0;    w1[2] = cp;
    }
}

// ---------------- kernel 4: GEMM2 (128x256) + residual + b_out ---------------
// Block: 128 m x 128 c (all of C), K=256 in smem. 8 warps (4 m x 2 n), warp 32x64.
#define S2 264
__global__ __launch_bounds__(256) void k_gemm2(const float* __restrict__ x,
                                               const float* __restrict__ b_out,
                                               float* __restrict__ out) {
    extern __shared__ __nv_bfloat16 sm2[];
    __nv_bfloat16* As = sm2;              // [128][S2]  V tile [m][h]
    __nv_bfloat16* Ws = sm2 + 128 * S2;   // [128][S2]  w_out  [c][h]
    int b = blockIdx.z;
    size_t m0 = (size_t)blockIdx.x * 128;
    int tid = threadIdx.x;

    const uint4* vsrc = (const uint4*)(g_V + ((size_t)b * MDIM + m0) * HDIM);
    for (int i = tid; i < 128 * 32; i += 256) {     // 32 uint4 per 256-elem row
        int m = i >> 5, q = i & 31;
        *((uint4*)(As + m * S2) + q) = vsrc[m * 32 + q];
    }
    const uint4* wsrc = (const uint4*)g_W2;
    for (int i = tid; i < 128 * 32; i += 256) {
        int c = i >> 5, q = i & 31;
        *((uint4*)(Ws + c * S2) + q) = wsrc[c * 32 + q];
    }
    __syncthreads();

    int wid = tid >> 5, lane = tid & 31;
    int wm = wid & 3, wn = wid >> 2;       // m offset wm*32, c offset wn*64
    int gid = lane >> 2, tg = lane & 3;

    float acc[2][8][4];
#pragma unroll
    for (int i = 0; i < 2; i++)
#pragma unroll
        for (int j = 0; j < 8; j++)
#pragma unroll
            for (int r = 0; r < 4; r++) acc[i][j][r] = 0.f;

#pragma unroll 4
    for (int kk = 0; kk < 256; kk += 16) {
        unsigned afr[2][4];
#pragma unroll
        for (int mt = 0; mt < 2; mt++) {
            const __nv_bfloat16* p = As + (wm * 32 + mt * 16 + gid) * S2 + kk + tg * 2;
            afr[mt][0] = *(const unsigned*)p;
            afr[mt][1] = *(const unsigned*)(p + 8 * S2);
            afr[mt][2] = *(const unsigned*)(p + 8);
            afr[mt][3] = *(const unsigned*)(p + 8 * S2 + 8);
        }
#pragma unroll
        for (int nt = 0; nt < 8; nt++) {
            const __nv_bfloat16* p = Ws + (wn * 64 + nt * 8 + gid) * S2 + kk + tg * 2;
            unsigned bfr[2] = { *(const unsigned*)p, *(const unsigned*)(p + 8) };
#pragma unroll
            for (int mt = 0; mt < 2; mt++) mma16816(acc[mt][nt], afr[mt], bfr);
        }
    }

    // epilogue: out[b][c][m] = x + acc + b_out[c]
#pragma unroll
    for (int mt = 0; mt < 2; mt++) {
#pragma unroll
        for (int nt = 0; nt < 8; nt++) {
            int c = wn * 64 + nt * 8 + tg * 2;
            float bo0 = b_out[c], bo1 = b_out[c + 1];
#pragma unroll
            for (int r = 0; r < 2; r++) {
                size_t m = m0 + wm * 32 + mt * 16 + gid + r * 8;
                size_t i0 = ((size_t)(b * CDIM + c)) * MDIM + m;
                size_t i1 = i0 + MDIM;
                out[i0] = x[i0] + acc[mt][nt][r * 2 + 0] + bo0;
                out[i1] = x[i1] + acc[mt][nt][r * 2 + 1] + bo1;
            }
        }
    }
}

// ---------------- launch ------------------------------------------------------
extern "C" void kernel_launch(void* const* d_in, const int* in_sizes, int n_in,
                              void* d_out, int out_size) {
    const float* x      = (const float*)d_in[0];
    const float* g_norm = (const float*)d_in[1];
    const float* w_in   = (const float*)d_in[2];
    const float* b_in   = (const float*)d_in[3];
    const float* w_dw   = (const float*)d_in[4];
    const float* b_dw   = (const float*)d_in[5];
    const float* w_out  = (const float*)d_in[6];
    const float* b_out  = (const float*)d_in[7];
    float* out = (float*)d_out;

    const int smem1 = (128 + 64 + 64) * S1 * (int)sizeof(__nv_bfloat16);  // 69632
    const int smem2 = 256 * S2 * (int)sizeof(__nv_bfloat16);              // 135168
    cudaFuncSetAttribute(k_gemm1, cudaFuncAttributeMaxDynamicSharedMemorySize, smem1);
    cudaFuncSetAttribute(k_gemm2, cudaFuncAttributeMaxDynamicSharedMemorySize, smem2);

    k_prep<<<256, 256>>>(w_in, g_norm, w_out);
    k_rms<<<dim3(TDIM / 64, FDIM, BATCH), 256>>>(x, g_norm);
    k_gemm1<<<dim3(MDIM / 128, HDIM / 64, BATCH), 256, smem1>>>(b_in);
    k_dw<<<dim3(TDIM / 128, FDIM, BATCH), 256>>>(w_dw, b_dw);
    k_gemm2<<<dim3(MDIM / 128, 1, BATCH), 256, smem2>>>(x, b_out, out);
}

// round 2
// speedup vs baseline: 1.0247x; 1.0247x over previous
#include <cuda_runtime.h>
#include <cuda_bf16.h>

#define BATCH 4
#define CDIM 128
#define FDIM 128
#define TDIM 512
#define HDIM 256
#define MDIM (FDIM*TDIM)   /* 65536 positions per batch */
#define EPSV 1e-6f

// ---------------- scratch (static device globals; no runtime alloc) ----------
__device__ __nv_bfloat16 g_Y[(size_t)BATCH * MDIM * CDIM];   //  64 MB  [b][m][c]
__device__ __nv_bfloat16 g_U[(size_t)BATCH * MDIM * HDIM];   // 128 MB  [b][m][h]
__device__ __nv_bfloat16 g_V[(size_t)BATCH * MDIM * HDIM];   // 128 MB  [b][m][h]
__device__ __nv_bfloat16 g_W1[2 * HDIM * CDIM];              // w_in * g_norm (bf16)
__device__ __nv_bfloat16 g_W2[CDIM * HDIM];                  // w_out (bf16)

// ---------------- kernel 0: weight prep --------------------------------------
__global__ void k_prep(const float* __restrict__ w_in,
                       const float* __restrict__ gn,
                       const float* __restrict__ w_out) {
    int i = blockIdx.x * 256 + threadIdx.x;
    if (i < 2 * HDIM * CDIM)
        g_W1[i] = __float2bfloat16(w_in[i] * gn[i & (CDIM - 1)]);
    if (i < CDIM * HDIM)
        g_W2[i] = __float2bfloat16(w_out[i]);
}

// ---------------- kernel 1: RMSNorm + transpose to [m][c] bf16 ---------------
__global__ __launch_bounds__(256) void k_rms(const float* __restrict__ x,
                                             const float* __restrict__ gn) {
    __shared__ float xs[CDIM][65];   // [c][t] padded
    __shared__ float ps[4][64];
    __shared__ float ssc[64];
    __shared__ float gs[CDIM];
    int b = blockIdx.z, f = blockIdx.y, t0 = blockIdx.x * 64;
    int tid = threadIdx.x;
    const float* xb = x + ((size_t)(b * CDIM) * FDIM + f) * TDIM + t0;
    for (int i = tid; i < CDIM * 64; i += 256) {
        int c = i >> 6, t = i & 63;
        xs[c][t] = xb[(size_t)c * FDIM * TDIM + t];
    }
    if (tid < CDIM) gs[tid] = gn[tid];
    __syncthreads();
    {
        int t = tid & 63, cs = (tid >> 6) * 32;
        float s = 0.f;
#pragma unroll
        for (int c = 0; c < 32; c++) { float v = xs[cs + c][t]; s += v * v; }
        ps[tid >> 6][t] = s;
    }
    __syncthreads();
    if (tid < 64) {
        float s = ps[0][tid] + ps[1][tid] + ps[2][tid] + ps[3][tid];
        ssc[tid] = rsqrtf(s * (1.0f / CDIM) + EPSV);
    }
    __syncthreads();
    __nv_bfloat16* yb = g_Y + ((size_t)b * MDIM + (size_t)f * TDIM + t0) * CDIM;
    for (int i = tid; i < 64 * CDIM; i += 256) {
        int t = i >> 7, c = i & 127;
        yb[(size_t)t * CDIM + c] = __float2bfloat16(xs[c][t] * ssc[t] * gs[c]);
    }
}

// ---------------- mma / ldmatrix helpers --------------------------------------
__device__ __forceinline__ void mma16816(float* d, const unsigned* a, const unsigned* bb) {
    asm volatile(
        "mma.sync.aligned.m16n8k16.row.col.f32.bf16.bf16.f32 "
        "{%0,%1,%2,%3},{%4,%5,%6,%7},{%8,%9},{%0,%1,%2,%3};\n"
        : "+f"(d[0]), "+f"(d[1]), "+f"(d[2]), "+f"(d[3])
        : "r"(a[0]), "r"(a[1]), "r"(a[2]), "r"(a[3]), "r"(bb[0]), "r"(bb[1]));
}
__device__ __forceinline__ unsigned sptr(const void* p) {
    unsigned r;
    asm("{.reg .u64 t; cvta.to.shared.u64 t, %1; cvt.u32.u64 %0, t;}" : "=r"(r) : "l"(p));
    return r;
}
__device__ __forceinline__ void ldsm4(unsigned addr, unsigned* r) {
    asm volatile("ldmatrix.sync.aligned.m8n8.x4.shared.b16 {%0,%1,%2,%3},[%4];"
                 : "=r"(r[0]), "=r"(r[1]), "=r"(r[2]), "=r"(r[3]) : "r"(addr));
}

// ---------------- kernel 2: GEMM1 (512x128 weights) + bias + GLU -------------
// Block: 128 m-positions x 64 h, full K=128 in smem. 8 warps (4 m x 2 n).
#define S1 136   // smem row stride (elems); 272B => rows spread over 128B window
__global__ __launch_bounds__(256, 2) void k_gemm1(const float* __restrict__ b_in) {
    extern __shared__ __nv_bfloat16 sm1[];
    __nv_bfloat16* As  = sm1;                 // [128][S1]  Y tile  [m][k]
    __nv_bfloat16* Was = sm1 + 128 * S1;      // [64][S1]   Wa rows [h][k]
    __nv_bfloat16* Wbs = Was + 64 * S1;       // [64][S1]   Wb rows
    int b = blockIdx.z;
    int h0 = blockIdx.y * 64;
    size_t m0 = (size_t)blockIdx.x * 128;
    int tid = threadIdx.x;

    const uint4* ysrc = (const uint4*)(g_Y + ((size_t)b * MDIM + m0) * CDIM);
    for (int i = tid; i < 128 * 16; i += 256) {      // 16 uint4 per 128-elem row
        int m = i >> 4, q = i & 15;
        *((uint4*)(As + m * S1) + q) = ysrc[m * 16 + q];
    }
    const uint4* wa = (const uint4*)(g_W1 + h0 * CDIM);
    const uint4* wb = (const uint4*)(g_W1 + (HDIM + h0) * CDIM);
    for (int i = tid; i < 64 * 16; i += 256) {
        int hh = i >> 4, q = i & 15;
        *((uint4*)(Was + hh * S1) + q) = wa[hh * 16 + q];
        *((uint4*)(Wbs + hh * S1) + q) = wb[hh * 16 + q];
    }
    __syncthreads();

    int wid = tid >> 5, lane = tid & 31;
    int wm = wid & 3, wn = wid >> 2;          // m offset wm*32, n offset wn*32
    int gid = lane >> 2, tg = lane & 3;

    // ldmatrix lane address bases (byte addresses into shared)
    unsigned aB[2], waB[2], wbB[2];
    {
        int arow = (lane & 15), akoff = (lane >> 4) * 8;
#pragma unroll
        for (int mt = 0; mt < 2; mt++)
            aB[mt] = sptr(As + (wm * 32 + mt * 16 + arow) * S1 + akoff);
        int brow = ((lane >> 4) << 3) + (lane & 7), bkoff = ((lane >> 3) & 1) * 8;
#pragma unroll
        for (int p = 0; p < 2; p++) {
            int n0 = wn * 32 + p * 16;
            waB[p] = sptr(Was + (n0 + brow) * S1 + bkoff);
            wbB[p] = sptr(Wbs + (n0 + brow) * S1 + bkoff);
        }
    }

    float accA[2][4][4], accB[2][4][4];
#pragma unroll
    for (int i = 0; i < 2; i++)
#pragma unroll
        for (int j = 0; j < 4; j++)
#pragma unroll
            for (int r = 0; r < 4; r++) { accA[i][j][r] = 0.f; accB[i][j][r] = 0.f; }

#pragma unroll
    for (int kk = 0; kk < 128; kk += 16) {
        unsigned afr[2][4], waf[2][4], wbf[2][4];
        ldsm4(aB[0] + kk * 2, afr[0]);
        ldsm4(aB[1] + kk * 2, afr[1]);
        ldsm4(waB[0] + kk * 2, waf[0]);
        ldsm4(waB[1] + kk * 2, waf[1]);
        ldsm4(wbB[0] + kk * 2, wbf[0]);
        ldsm4(wbB[1] + kk * 2, wbf[1]);
#pragma unroll
        for (int nt = 0; nt < 4; nt++) {
            const unsigned* bA = &waf[nt >> 1][(nt & 1) * 2];
            const unsigned* bB = &wbf[nt >> 1][(nt & 1) * 2];
#pragma unroll
            for (int mt = 0; mt < 2; mt++) {
                mma16816(accA[mt][nt], afr[mt], bA);
                mma16816(accB[mt][nt], afr[mt], bB);
            }
        }
    }

    // epilogue: bias + GLU, write bf16 pairs to g_U[b][m][h]
#pragma unroll
    for (int mt = 0; mt < 2; mt++) {
#pragma unroll
        for (int nt = 0; nt < 4; nt++) {
            int hg = h0 + wn * 32 + nt * 8 + tg * 2;
            float bi0 = b_in[hg],        bi1 = b_in[hg + 1];
            float bg0 = b_in[HDIM + hg], bg1 = b_in[HDIM + hg + 1];
#pragma unroll
            for (int r = 0; r < 2; r++) {
                size_t m = m0 + wm * 32 + mt * 16 + gid + r * 8;
                float a0 = accA[mt][nt][r * 2 + 0] + bi0;
                float a1 = accA[mt][nt][r * 2 + 1] + bi1;
                float g0 = accB[mt][nt][r * 2 + 0] + bg0;
                float g1 = accB[mt][nt][r * 2 + 1] + bg1;
                float u0 = a0 / (1.f + __expf(-g0));
                float u1 = a1 / (1.f + __expf(-g1));
                *(__nv_bfloat162*)(g_U + ((size_t)b * MDIM + m) * HDIM + hg) =
                    __floats2bfloat162_rn(u0, u1);
            }
        }
    }
}

// ---------------- kernel 3: depthwise 3x3 (F same-pad, T causal) + SiLU ------
// Each thread handles 4 h-channels (uint2 loads) and sweeps 32 t with a
// register sliding window.
__device__ __forceinline__ void ld4bf(const __nv_bfloat16* p, float* o) {
    uint2 v = *(const uint2*)p;
    float2 f0 = __bfloat1622float2(*(__nv_bfloat162*)&v.x);
    float2 f1 = __bfloat1622float2(*(__nv_bfloat162*)&v.y);
    o[0] = f0.x; o[1] = f0.y; o[2] = f1.x; o[3] = f1.y;
}
__global__ __launch_bounds__(256) void k_dw(const float* __restrict__ w_dw,
                                            const float* __restrict__ b_dw) {
    int tid = threadIdx.x;
    int h = (tid & 63) * 4;          // 4 channels per thread
    int tseg = tid >> 6;             // 0..3
    int b = blockIdx.z, f = blockIdx.y;
    int t0 = blockIdx.x * 128 + tseg * 32;

    float wd[4][9], bd[4];
#pragma unroll
    for (int j = 0; j < 4; j++) {
#pragma unroll
        for (int i = 0; i < 9; i++) wd[j][i] = w_dw[(h + j) * 9 + i];
        bd[j] = b_dw[h + j];
    }
    bool fm = (f > 0), fp = (f < FDIM - 1);
    const __nv_bfloat16* base = g_U + (size_t)b * MDIM * HDIM + h;
    size_t rowm = fm ? (size_t)(f - 1) * TDIM * HDIM : 0;
    size_t row0 = (size_t)f * TDIM * HDIM;
    size_t rowp = fp ? (size_t)(f + 1) * TDIM * HDIM : 0;

    float a0[3][4], a1[3][4];        // t-2, t-1 windows: [frow][h-lane]
#pragma unroll
    for (int r = 0; r < 3; r++)
#pragma unroll
        for (int j = 0; j < 4; j++) { a0[r][j] = 0.f; a1[r][j] = 0.f; }
#pragma unroll
    for (int jj = 0; jj < 2; jj++) {
        int t = t0 - 2 + jj;
        float (*w)[4] = jj ? a1 : a0;
        if (t >= 0) {
            if (fm) ld4bf(base + rowm + (size_t)t * HDIM, w[0]);
            ld4bf(base + row0 + (size_t)t * HDIM, w[1]);
            if (fp) ld4bf(base + rowp + (size_t)t * HDIM, w[2]);
        }
    }
    __nv_bfloat16* vout = g_V + ((size_t)b * MDIM + (size_t)f * TDIM + t0) * HDIM + h;
#pragma unroll 4
    for (int t = t0; t < t0 + 32; t++) {
        float cur[3][4];
#pragma unroll
        for (int j = 0; j < 4; j++) { cur[0][j] = 0.f; cur[2][j] = 0.f; }
        if (fm) ld4bf(base + rowm + (size_t)t * HDIM, cur[0]);
        ld4bf(base + row0 + (size_t)t * HDIM, cur[1]);
        if (fp) ld4bf(base + rowp + (size_t)t * HDIM, cur[2]);
        float res[4];
#pragma unroll
        for (int j = 0; j < 4; j++) {
            float acc = bd[j];
            acc += a0[0][j] * wd[j][0] + a1[0][j] * wd[j][1] + cur[0][j] * wd[j][2];
            acc += a0[1][j] * wd[j][3] + a1[1][j] * wd[j][4] + cur[1][j] * wd[j][5];
            acc += a0[2][j] * wd[j][6] + a1[2][j] * wd[j][7] + cur[2][j] * wd[j][8];
            res[j] = acc / (1.f + __expf(-acc));
        }
        uint2 pk;
        __nv_bfloat162 p0 = __floats2bfloat162_rn(res[0], res[1]);
        __nv_bfloat162 p1 = __floats2bfloat162_rn(res[2], res[3]);
        pk.x = *(unsigned*)&p0; pk.y = *(unsigned*)&p1;
        *(uint2*)vout = pk;
        vout += HDIM;
#pragma unroll
        for (int r = 0; r < 3; r++)
#pragma unroll
            for (int j = 0; j < 4; j++) { a0[r][j] = a1[r][j]; a1[r][j] = cur[r][j]; }
    }
}

// ---------------- kernel 4: GEMM2 (128x256) + residual + b_out ---------------
// Block: 128 m x 128 c (all of C), K=256 in smem. 8 warps (4 m x 2 n), warp 32x64.
#define S2 264
__global__ __launch_bounds__(256) void k_gemm2(const float* __restrict__ x,
                                               const float* __restrict__ b_out,
                                               float* __restrict__ out) {
    extern __shared__ __nv_bfloat16 sm2[];
    __nv_bfloat16* As = sm2;              // [128][S2]  V tile [m][h]
    __nv_bfloat16* Ws = sm2 + 128 * S2;   // [128][S2]  w_out  [c][h]
    int b = blockIdx.z;
    size_t m0 = (size_t)blockIdx.x * 128;
    int tid = threadIdx.x;

    const uint4* vsrc = (const uint4*)(g_V + ((size_t)b * MDIM + m0) * HDIM);
    for (int i = tid; i < 128 * 32; i += 256) {     // 32 uint4 per 256-elem row
        int m = i >> 5, q = i & 31;
        *((uint4*)(As + m * S2) + q) = vsrc[m * 32 + q];
    }
    const uint4* wsrc = (const uint4*)g_W2;
    for (int i = tid; i < 128 * 32; i += 256) {
        int c = i >> 5, q = i & 31;
        *((uint4*)(Ws + c * S2) + q) = wsrc[c * 32 + q];
    }
    __syncthreads();

    int wid = tid >> 5, lane = tid & 31;
    int wm = wid & 3, wn = wid >> 2;       // m offset wm*32, c offset wn*64
    int gid = lane >> 2, tg = lane & 3;

    unsigned aB[2], wB[4];
    {
        int arow = (lane & 15), akoff = (lane >> 4) * 8;
#pragma unroll
        for (int mt = 0; mt < 2; mt++)
            aB[mt] = sptr(As + (wm * 32 + mt * 16 + arow) * S2 + akoff);
        int brow = ((lane >> 4) << 3) + (lane & 7), bkoff = ((lane >> 3) & 1) * 8;
#pragma unroll
        for (int p = 0; p < 4; p++) {
            int n0 = wn * 64 + p * 16;
            wB[p] = sptr(Ws + (n0 + brow) * S2 + bkoff);
        }
    }

    float acc[2][8][4];
#pragma unroll
    for (int i = 0; i < 2; i++)
#pragma unroll
        for (int j = 0; j < 8; j++)
#pragma unroll
            for (int r = 0; r < 4; r++) acc[i][j][r] = 0.f;

#pragma unroll 4
    for (int kk = 0; kk < 256; kk += 16) {
        unsigned afr[2][4], bfr[4][4];
        ldsm4(aB[0] + kk * 2, afr[0]);
        ldsm4(aB[1] + kk * 2, afr[1]);
#pragma unroll
        for (int p = 0; p < 4; p++) ldsm4(wB[p] + kk * 2, bfr[p]);
#pragma unroll
        for (int nt = 0; nt < 8; nt++) {
            const unsigned* bb = &bfr[nt >> 1][(nt & 1) * 2];
#pragma unroll
            for (int mt = 0; mt < 2; mt++) mma16816(acc[mt][nt], afr[mt], bb);
        }
    }

    // epilogue: out[b][c][m] = x + acc + b_out[c]
#pragma unroll
    for (int mt = 0; mt < 2; mt++) {
#pragma unroll
        for (int nt = 0; nt < 8; nt++) {
            int c = wn * 64 + nt * 8 + tg * 2;
            float bo0 = b_out[c], bo1 = b_out[c + 1];
#pragma unroll
            for (int r = 0; r < 2; r++) {
                size_t m = m0 + wm * 32 + mt * 16 + gid + r * 8;
                size_t i0 = ((size_t)(b * CDIM + c)) * MDIM + m;
                size_t i1 = i0 + MDIM;
                out[i0] = x[i0] + acc[mt][nt][r * 2 + 0] + bo0;
                out[i1] = x[i1] + acc[mt][nt][r * 2 + 1] + bo1;
            }
        }
    }
}

// ---------------- launch ------------------------------------------------------
extern "C" void kernel_launch(void* const* d_in, const int* in_sizes, int n_in,
                              void* d_out, int out_size) {
    const float* x      = (const float*)d_in[0];
    const float* g_norm = (const float*)d_in[1];
    const float* w_in   = (const float*)d_in[2];
    const float* b_in   = (const float*)d_in[3];
    const float* w_dw   = (const float*)d_in[4];
    const float* b_dw   = (const float*)d_in[5];
    const float* w_out  = (const float*)d_in[6];
    const float* b_out  = (const float*)d_in[7];
    float* out = (float*)d_out;

    const int smem1 = (128 + 64 + 64) * S1 * (int)sizeof(__nv_bfloat16);  // 69632
    const int smem2 = 256 * S2 * (int)sizeof(__nv_bfloat16);              // 135168
    cudaFuncSetAttribute(k_gemm1, cudaFuncAttributeMaxDynamicSharedMemorySize, smem1);
    cudaFuncSetAttribute(k_gemm2, cudaFuncAttributeMaxDynamicSharedMemorySize, smem2);

    k_prep<<<256, 256>>>(w_in, g_norm, w_out);
    k_rms<<<dim3(TDIM / 64, FDIM, BATCH), 256>>>(x, g_norm);
    k_gemm1<<<dim3(MDIM / 128, HDIM / 64, BATCH), 256, smem1>>>(b_in);
    k_dw<<<dim3(TDIM / 128, FDIM, BATCH), 256>>>(w_dw, b_dw);
    k_gemm2<<<dim3(MDIM / 128, 1, BATCH), 256, smem2>>>(x, b_out, out);
}

// round 3
// speedup vs baseline: 1.0956x; 1.0692x over previous
#include <cuda_runtime.h>
#include <cuda_bf16.h>

#define BATCH 4
#define CDIM 128
#define FDIM 128
#define TDIM 512
#define HDIM 256
#define MDIM (FDIM*TDIM)   /* 65536 positions per batch */
#define EPSV 1e-6f

// ---------------- scratch (static device globals; no runtime alloc) ----------
__device__ __nv_bfloat16 g_Y[(size_t)BATCH * MDIM * CDIM];   //  64 MB  [b][m][c]
__device__ __nv_bfloat16 g_U[(size_t)BATCH * MDIM * HDIM];   // 128 MB  [b][m][h]
__device__ __nv_bfloat16 g_V[(size_t)BATCH * MDIM * HDIM];   // 128 MB  [b][m][h]
__device__ __nv_bfloat16 g_W1[2 * HDIM * CDIM];              // w_in * g_norm (bf16)
__device__ __nv_bfloat16 g_W2[CDIM * HDIM];                  // w_out (bf16)

// ---------------- kernel 0: weight prep --------------------------------------
__global__ void k_prep(const float* __restrict__ w_in,
                       const float* __restrict__ gn,
                       const float* __restrict__ w_out) {
    int i = blockIdx.x * 256 + threadIdx.x;
    if (i < 2 * HDIM * CDIM)
        g_W1[i] = __float2bfloat16(w_in[i] * gn[i & (CDIM - 1)]);
    if (i < CDIM * HDIM)
        g_W2[i] = __float2bfloat16(w_out[i]);
}

// ---------------- kernel 1: RMSNorm + transpose to [m][c] bf16 ---------------
__global__ __launch_bounds__(256) void k_rms(const float* __restrict__ x,
                                             const float* __restrict__ gn) {
    __shared__ float xs[CDIM][65];   // [c][t] padded
    __shared__ float ps[4][64];
    __shared__ float ssc[64];
    __shared__ float gs[CDIM];
    int b = blockIdx.z, f = blockIdx.y, t0 = blockIdx.x * 64;
    int tid = threadIdx.x;
    const float* xb = x + ((size_t)(b * CDIM) * FDIM + f) * TDIM + t0;
    for (int i = tid; i < CDIM * 64; i += 256) {
        int c = i >> 6, t = i & 63;
        xs[c][t] = xb[(size_t)c * FDIM * TDIM + t];
    }
    if (tid < CDIM) gs[tid] = gn[tid];
    __syncthreads();
    {
        int t = tid & 63, cs = (tid >> 6) * 32;
        float s = 0.f;
#pragma unroll
        for (int c = 0; c < 32; c++) { float v = xs[cs + c][t]; s += v * v; }
        ps[tid >> 6][t] = s;
    }
    __syncthreads();
    if (tid < 64) {
        float s = ps[0][tid] + ps[1][tid] + ps[2][tid] + ps[3][tid];
        ssc[tid] = rsqrtf(s * (1.0f / CDIM) + EPSV);
    }
    __syncthreads();
    __nv_bfloat16* yb = g_Y + ((size_t)b * MDIM + (size_t)f * TDIM + t0) * CDIM;
    for (int i = tid; i < 64 * CDIM; i += 256) {
        int t = i >> 7, c = i & 127;
        yb[(size_t)t * CDIM + c] = __float2bfloat16(xs[c][t] * ssc[t] * gs[c]);
    }
}

// ---------------- mma / ldmatrix helpers --------------------------------------
__device__ __forceinline__ void mma16816(float* d, const unsigned* a, const unsigned* bb) {
    asm volatile(
        "mma.sync.aligned.m16n8k16.row.col.f32.bf16.bf16.f32 "
        "{%0,%1,%2,%3},{%4,%5,%6,%7},{%8,%9},{%0,%1,%2,%3};\n"
        : "+f"(d[0]), "+f"(d[1]), "+f"(d[2]), "+f"(d[3])
        : "r"(a[0]), "r"(a[1]), "r"(a[2]), "r"(a[3]), "r"(bb[0]), "r"(bb[1]));
}
__device__ __forceinline__ unsigned sptr(const void* p) {
    unsigned r;
    asm("{.reg .u64 t; cvta.to.shared.u64 t, %1; cvt.u32.u64 %0, t;}" : "=r"(r) : "l"(p));
    return r;
}
__device__ __forceinline__ void ldsm4(unsigned addr, unsigned* r) {
    asm volatile("ldmatrix.sync.aligned.m8n8.x4.shared.b16 {%0,%1,%2,%3},[%4];"
                 : "=r"(r[0]), "=r"(r[1]), "=r"(r[2]), "=r"(r[3]) : "r"(addr));
}

// ---------------- kernel 2: GEMM1 (512x128 weights) + bias + GLU -------------
// Block: 128 m x 128 h (256 weight rows), full K=128 in smem.
// 512 threads = 16 warps (4 m x 4 n). grid.y=2 => Y read only twice.
#define S1 136   // smem row stride (elems)
__global__ __launch_bounds__(512, 1) void k_gemm1(const float* __restrict__ b_in) {
    extern __shared__ __nv_bfloat16 sm1[];
    __nv_bfloat16* As  = sm1;                  // [128][S1]  Y tile  [m][k]
    __nv_bfloat16* Was = sm1 + 128 * S1;       // [128][S1]  Wa rows [h][k]
    __nv_bfloat16* Wbs = Was + 128 * S1;       // [128][S1]  Wb rows
    int b = blockIdx.z;
    int h0 = blockIdx.y * 128;
    size_t m0 = (size_t)blockIdx.x * 128;
    int tid = threadIdx.x;

    const uint4* ysrc = (const uint4*)(g_Y + ((size_t)b * MDIM + m0) * CDIM);
    for (int i = tid; i < 128 * 16; i += 512) {      // 16 uint4 per 128-elem row
        int m = i >> 4, q = i & 15;
        *((uint4*)(As + m * S1) + q) = ysrc[m * 16 + q];
    }
    const uint4* wa = (const uint4*)(g_W1 + h0 * CDIM);
    const uint4* wb = (const uint4*)(g_W1 + (HDIM + h0) * CDIM);
    for (int i = tid; i < 128 * 16; i += 512) {
        int hh = i >> 4, q = i & 15;
        *((uint4*)(Was + hh * S1) + q) = wa[hh * 16 + q];
        *((uint4*)(Wbs + hh * S1) + q) = wb[hh * 16 + q];
    }
    __syncthreads();

    int wid = tid >> 5, lane = tid & 31;
    int wm = wid & 3, wn = wid >> 2;          // m offset wm*32, n offset wn*32
    int gid = lane >> 2, tg = lane & 3;

    // ldmatrix lane address bases (byte addresses into shared)
    unsigned aB[2], waB[2], wbB[2];
    {
        int arow = (lane & 15), akoff = (lane >> 4) * 8;
#pragma unroll
        for (int mt = 0; mt < 2; mt++)
            aB[mt] = sptr(As + (wm * 32 + mt * 16 + arow) * S1 + akoff);
        int brow = ((lane >> 4) << 3) + (lane & 7), bkoff = ((lane >> 3) & 1) * 8;
#pragma unroll
        for (int p = 0; p < 2; p++) {
            int n0 = wn * 32 + p * 16;
            waB[p] = sptr(Was + (n0 + brow) * S1 + bkoff);
            wbB[p] = sptr(Wbs + (n0 + brow) * S1 + bkoff);
        }
    }

    float accA[2][4][4], accB[2][4][4];
#pragma unroll
    for (int i = 0; i < 2; i++)
#pragma unroll
        for (int j = 0; j < 4; j++)
#pragma unroll
            for (int r = 0; r < 4; r++) { accA[i][j][r] = 0.f; accB[i][j][r] = 0.f; }

#pragma unroll
    for (int kk = 0; kk < 128; kk += 16) {
        unsigned afr[2][4], waf[2][4], wbf[2][4];
        ldsm4(aB[0] + kk * 2, afr[0]);
        ldsm4(aB[1] + kk * 2, afr[1]);
        ldsm4(waB[0] + kk * 2, waf[0]);
        ldsm4(waB[1] + kk * 2, waf[1]);
        ldsm4(wbB[0] + kk * 2, wbf[0]);
        ldsm4(wbB[1] + kk * 2, wbf[1]);
#pragma unroll
        for (int nt = 0; nt < 4; nt++) {
            const unsigned* bA = &waf[nt >> 1][(nt & 1) * 2];
            const unsigned* bB = &wbf[nt >> 1][(nt & 1) * 2];
#pragma unroll
            for (int mt = 0; mt < 2; mt++) {
                mma16816(accA[mt][nt], afr[mt], bA);
                mma16816(accB[mt][nt], afr[mt], bB);
            }
        }
    }

    // epilogue: bias + GLU, write bf16 pairs to g_U[b][m][h]
#pragma unroll
    for (int mt = 0; mt < 2; mt++) {
#pragma unroll
        for (int nt = 0; nt < 4; nt++) {
            int hg = h0 + wn * 32 + nt * 8 + tg * 2;
            float bi0 = b_in[hg],        bi1 = b_in[hg + 1];
            float bg0 = b_in[HDIM + hg], bg1 = b_in[HDIM + hg + 1];
#pragma unroll
            for (int r = 0; r < 2; r++) {
                size_t m = m0 + wm * 32 + mt * 16 + gid + r * 8;
                float a0 = accA[mt][nt][r * 2 + 0] + bi0;
                float a1 = accA[mt][nt][r * 2 + 1] + bi1;
                float g0 = accB[mt][nt][r * 2 + 0] + bg0;
                float g1 = accB[mt][nt][r * 2 + 1] + bg1;
                float u0 = a0 / (1.f + __expf(-g0));
                float u1 = a1 / (1.f + __expf(-g1));
                *(__nv_bfloat162*)(g_U + ((size_t)b * MDIM + m) * HDIM + hg) =
                    __floats2bfloat162_rn(u0, u1);
            }
        }
    }
}

// ---------------- kernel 3: depthwise 3x3 (F same-pad, T causal) + SiLU ------
// Shared-memory staged: block = one f row x 64 t. Stage U[3][66][256] bf16
// (zero-filled halo => no edge predicates in the hot loop), then register
// sliding window fed from smem. High-MLP front-batched staging loads.
#define DWT 64
#define DWSM (3 * (DWT + 2) * HDIM)   /* elems: 3*66*256 = 50688, 101376 B */
__device__ __forceinline__ void ld4sm(const __nv_bfloat16* p, float* o) {
    uint2 v = *(const uint2*)p;
    float2 f0 = __bfloat1622float2(*(__nv_bfloat162*)&v.x);
    float2 f1 = __bfloat1622float2(*(__nv_bfloat162*)&v.y);
    o[0] = f0.x; o[1] = f0.y; o[2] = f1.x; o[3] = f1.y;
}
__global__ __launch_bounds__(256) void k_dw(const float* __restrict__ w_dw,
                                            const float* __restrict__ b_dw) {
    extern __shared__ __nv_bfloat16 us[];   // [3][66][HDIM]
    int tid = threadIdx.x;
    int b = blockIdx.z, f = blockIdx.y, t0 = blockIdx.x * DWT;

    // ---- stage (independent uint4 loads, zero halo) ----
    const size_t HT = (size_t)TDIM * HDIM;
    const __nv_bfloat16* ub = g_U + (size_t)b * MDIM * HDIM;
    for (int i = tid; i < 3 * (DWT + 2) * 32; i += 256) {
        int r = i / ((DWT + 2) * 32);
        int rem = i - r * ((DWT + 2) * 32);
        int tt = rem >> 5, q = rem & 31;
        int ff = f - 1 + r, t = t0 - 2 + tt;
        uint4 v = make_uint4(0u, 0u, 0u, 0u);
        if (ff >= 0 && ff < FDIM && t >= 0)
            v = *(const uint4*)(ub + (size_t)ff * HT + (size_t)t * HDIM + q * 8);
        *((uint4*)(us + (r * (DWT + 2) + tt) * HDIM) + q) = v;
    }
    __syncthreads();

    // ---- per-thread: 4 h-channels x 16 t-steps ----
    int h = (tid & 63) * 4;
    int tseg = tid >> 6;             // 0..3
    int lt0 = tseg * 16;

    float wd[4][9], bd[4];
#pragma unroll
    for (int j = 0; j < 4; j++) {
#pragma unroll
        for (int i = 0; i < 9; i++) wd[j][i] = w_dw[(h + j) * 9 + i];
        bd[j] = b_dw[h + j];
    }

    float a0[3][4], a1[3][4];
#pragma unroll
    for (int r = 0; r < 3; r++) {
        ld4sm(us + (r * (DWT + 2) + lt0) * HDIM + h, a0[r]);
        ld4sm(us + (r * (DWT + 2) + lt0 + 1) * HDIM + h, a1[r]);
    }

    __nv_bfloat16* vout = g_V + ((size_t)b * MDIM + (size_t)f * TDIM + t0 + lt0) * HDIM + h;
#pragma unroll
    for (int j = 0; j < 16; j++) {
        float cur[3][4];
#pragma unroll
        for (int r = 0; r < 3; r++)
            ld4sm(us + (r * (DWT + 2) + lt0 + 2 + j) * HDIM + h, cur[r]);
        float res[4];
#pragma unroll
        for (int q = 0; q < 4; q++) {
            float acc = bd[q];
            acc += a0[0][q] * wd[q][0] + a1[0][q] * wd[q][1] + cur[0][q] * wd[q][2];
            acc += a0[1][q] * wd[q][3] + a1[1][q] * wd[q][4] + cur[1][q] * wd[q][5];
            acc += a0[2][q] * wd[q][6] + a1[2][q] * wd[q][7] + cur[2][q] * wd[q][8];
            res[q] = acc / (1.f + __expf(-acc));
        }
        uint2 pk;
        __nv_bfloat162 p0 = __floats2bfloat162_rn(res[0], res[1]);
        __nv_bfloat162 p1 = __floats2bfloat162_rn(res[2], res[3]);
        pk.x = *(unsigned*)&p0; pk.y = *(unsigned*)&p1;
        *(uint2*)vout = pk;
        vout += HDIM;
#pragma unroll
        for (int r = 0; r < 3; r++)
#pragma unroll
            for (int q = 0; q < 4; q++) { a0[r][q] = a1[r][q]; a1[r][q] = cur[r][q]; }
    }
}

// ---------------- kernel 4: GEMM2 (128x256) + residual + b_out ---------------
// Block: 128 m x 128 c (all of C), K=256 in smem. 8 warps (4 m x 2 n), warp 32x64.
#define S2 264
__global__ __launch_bounds__(256) void k_gemm2(const float* __restrict__ x,
                                               const float* __restrict__ b_out,
                                               float* __restrict__ out) {
    extern __shared__ __nv_bfloat16 sm2[];
    __nv_bfloat16* As = sm2;              // [128][S2]  V tile [m][h]
    __nv_bfloat16* Ws = sm2 + 128 * S2;   // [128][S2]  w_out  [c][h]
    int b = blockIdx.z;
    size_t m0 = (size_t)blockIdx.x * 128;
    int tid = threadIdx.x;

    const uint4* vsrc = (const uint4*)(g_V + ((size_t)b * MDIM + m0) * HDIM);
    for (int i = tid; i < 128 * 32; i += 256) {     // 32 uint4 per 256-elem row
        int m = i >> 5, q = i & 31;
        *((uint4*)(As + m * S2) + q) = vsrc[m * 32 + q];
    }
    const uint4* wsrc = (const uint4*)g_W2;
    for (int i = tid; i < 128 * 32; i += 256) {
        int c = i >> 5, q = i & 31;
        *((uint4*)(Ws + c * S2) + q) = wsrc[c * 32 + q];
    }
    __syncthreads();

    int wid = tid >> 5, lane = tid & 31;
    int wm = wid & 3, wn = wid >> 2;       // m offset wm*32, c offset wn*64
    int gid = lane >> 2, tg = lane & 3;

    unsigned aB[2], wB[4];
    {
        int arow = (lane & 15), akoff = (lane >> 4) * 8;
#pragma unroll
        for (int mt = 0; mt < 2; mt++)
            aB[mt] = sptr(As + (wm * 32 + mt * 16 + arow) * S2 + akoff);
        int brow = ((lane >> 4) << 3) + (lane & 7), bkoff = ((lane >> 3) & 1) * 8;
#pragma unroll
        for (int p = 0; p < 4; p++) {
            int n0 = wn * 64 + p * 16;
            wB[p] = sptr(Ws + (n0 + brow) * S2 + bkoff);
        }
    }

    float acc[2][8][4];
#pragma unroll
    for (int i = 0; i < 2; i++)
#pragma unroll
        for (int j = 0; j < 8; j++)
#pragma unroll
            for (int r = 0; r < 4; r++) acc[i][j][r] = 0.f;

#pragma unroll 4
    for (int kk = 0; kk < 256; kk += 16) {
        unsigned afr[2][4], bfr[4][4];
        ldsm4(aB[0] + kk * 2, afr[0]);
        ldsm4(aB[1] + kk * 2, afr[1]);
#pragma unroll
        for (int p = 0; p < 4; p++) ldsm4(wB[p] + kk * 2, bfr[p]);
#pragma unroll
        for (int nt = 0; nt < 8; nt++) {
            const unsigned* bb = &bfr[nt >> 1][(nt & 1) * 2];
#pragma unroll
            for (int mt = 0; mt < 2; mt++) mma16816(acc[mt][nt], afr[mt], bb);
        }
    }

    // epilogue: out[b][c][m] = x + acc + b_out[c]
#pragma unroll
    for (int mt = 0; mt < 2; mt++) {
#pragma unroll
        for (int nt = 0; nt < 8; nt++) {
            int c = wn * 64 + nt * 8 + tg * 2;
            float bo0 = b_out[c], bo1 = b_out[c + 1];
#pragma unroll
            for (int r = 0; r < 2; r++) {
                size_t m = m0 + wm * 32 + mt * 16 + gid + r * 8;
                size_t i0 = ((size_t)(b * CDIM + c)) * MDIM + m;
                size_t i1 = i0 + MDIM;
                out[i0] = x[i0] + acc[mt][nt][r * 2 + 0] + bo0;
                out[i1] = x[i1] + acc[mt][nt][r * 2 + 1] + bo1;
            }
        }
    }
}

// ---------------- launch ------------------------------------------------------
extern "C" void kernel_launch(void* const* d_in, const int* in_sizes, int n_in,
                              void* d_out, int out_size) {
    const float* x      = (const float*)d_in[0];
    const float* g_norm = (const float*)d_in[1];
    const float* w_in   = (const float*)d_in[2];
    const float* b_in   = (const float*)d_in[3];
    const float* w_dw   = (const float*)d_in[4];
    const float* b_dw   = (const float*)d_in[5];
    const float* w_out  = (const float*)d_in[6];
    const float* b_out  = (const float*)d_in[7];
    float* out = (float*)d_out;

    const int smem1 = 384 * S1 * (int)sizeof(__nv_bfloat16);   // 104448
    const int smem2 = 256 * S2 * (int)sizeof(__nv_bfloat16);   // 135168
    const int smemd = DWSM * (int)sizeof(__nv_bfloat16);       // 101376
    cudaFuncSetAttribute(k_gemm1, cudaFuncAttributeMaxDynamicSharedMemorySize, smem1);
    cudaFuncSetAttribute(k_gemm2, cudaFuncAttributeMaxDynamicSharedMemorySize, smem2);
    cudaFuncSetAttribute(k_dw,    cudaFuncAttributeMaxDynamicSharedMemorySize, smemd);

    k_prep<<<256, 256>>>(w_in, g_norm, w_out);
    k_rms<<<dim3(TDIM / 64, FDIM, BATCH), 256>>>(x, g_norm);
    k_gemm1<<<dim3(MDIM / 128, HDIM / 128, BATCH), 512, smem1>>>(b_in);
    k_dw<<<dim3(TDIM / DWT, FDIM, BATCH), 256, smemd>>>(w_dw, b_dw);
    k_gemm2<<<dim3(MDIM / 128, 1, BATCH), 256, smem2>>>(x, b_out, out);
}

// round 4
// speedup vs baseline: 1.1727x; 1.0703x over previous
#include <cuda_runtime.h>
#include <cuda_bf16.h>

#define BATCH 4
#define CDIM 128
#define FDIM 128
#define TDIM 512
#define HDIM 256
#define MDIM (FDIM*TDIM)   /* 65536 positions per batch */
#define EPSV 1e-6f

// ---------------- scratch (static device globals; no runtime alloc) ----------
__device__ __nv_bfloat16 g_Y[(size_t)BATCH * MDIM * CDIM];   //  64 MB  [b][m][c]
__device__ __nv_bfloat16 g_U[(size_t)BATCH * MDIM * HDIM];   // 128 MB  [b][m][h]
__device__ __nv_bfloat16 g_W1[2 * HDIM * CDIM];              // w_in * g_norm (bf16)
__device__ __nv_bfloat16 g_W2[CDIM * HDIM];                  // w_out (bf16)

// ---------------- kernel 0: weight prep --------------------------------------
__global__ void k_prep(const float* __restrict__ w_in,
                       const float* __restrict__ gn,
                       const float* __restrict__ w_out) {
    int i = blockIdx.x * 256 + threadIdx.x;
    if (i < 2 * HDIM * CDIM)
        g_W1[i] = __float2bfloat16(w_in[i] * gn[i & (CDIM - 1)]);
    if (i < CDIM * HDIM)
        g_W2[i] = __float2bfloat16(w_out[i]);
}

// ---------------- kernel 1: RMSNorm + transpose to [m][c] bf16 ---------------
__global__ __launch_bounds__(256) void k_rms(const float* __restrict__ x,
                                             const float* __restrict__ gn) {
    __shared__ float xs[CDIM][65];   // [c][t] padded
    __shared__ float ps[4][64];
    __shared__ float ssc[64];
    __shared__ float gs[CDIM];
    int b = blockIdx.z, f = blockIdx.y, t0 = blockIdx.x * 64;
    int tid = threadIdx.x;
    const float* xb = x + ((size_t)(b * CDIM) * FDIM + f) * TDIM + t0;
    for (int i = tid; i < CDIM * 64; i += 256) {
        int c = i >> 6, t = i & 63;
        xs[c][t] = xb[(size_t)c * FDIM * TDIM + t];
    }
    if (tid < CDIM) gs[tid] = gn[tid];
    __syncthreads();
    {
        int t = tid & 63, cs = (tid >> 6) * 32;
        float s = 0.f;
#pragma unroll
        for (int c = 0; c < 32; c++) { float v = xs[cs + c][t]; s += v * v; }
        ps[tid >> 6][t] = s;
    }
    __syncthreads();
    if (tid < 64) {
        float s = ps[0][tid] + ps[1][tid] + ps[2][tid] + ps[3][tid];
        ssc[tid] = rsqrtf(s * (1.0f / CDIM) + EPSV);
    }
    __syncthreads();
    __nv_bfloat16* yb = g_Y + ((size_t)b * MDIM + (size_t)f * TDIM + t0) * CDIM;
    for (int i = tid; i < 64 * CDIM; i += 256) {
        int t = i >> 7, c = i & 127;
        yb[(size_t)t * CDIM + c] = __float2bfloat16(xs[c][t] * ssc[t] * gs[c]);
    }
}

// ---------------- mma / ldmatrix helpers --------------------------------------
__device__ __forceinline__ void mma16816(float* d, const unsigned* a, const unsigned* bb) {
    asm volatile(
        "mma.sync.aligned.m16n8k16.row.col.f32.bf16.bf16.f32 "
        "{%0,%1,%2,%3},{%4,%5,%6,%7},{%8,%9},{%0,%1,%2,%3};\n"
        : "+f"(d[0]), "+f"(d[1]), "+f"(d[2]), "+f"(d[3])
        : "r"(a[0]), "r"(a[1]), "r"(a[2]), "r"(a[3]), "r"(bb[0]), "r"(bb[1]));
}
__device__ __forceinline__ unsigned sptr(const void* p) {
    unsigned r;
    asm("{.reg .u64 t; cvta.to.shared.u64 t, %1; cvt.u32.u64 %0, t;}" : "=r"(r) : "l"(p));
    return r;
}
__device__ __forceinline__ void ldsm4(unsigned addr, unsigned* r) {
    asm volatile("ldmatrix.sync.aligned.m8n8.x4.shared.b16 {%0,%1,%2,%3},[%4];"
                 : "=r"(r[0]), "=r"(r[1]), "=r"(r[2]), "=r"(r[3]) : "r"(addr));
}

// ---------------- kernel 2: GEMM1 (512x128 weights) + bias + GLU -------------
// Block: 128 m x 128 h (256 weight rows), full K=128 in smem.
// 512 threads = 16 warps (4 m x 4 n). grid.y=2 => Y read only twice.
#define S1 136   // smem row stride (elems)
__global__ __launch_bounds__(512, 1) void k_gemm1(const float* __restrict__ b_in) {
    extern __shared__ __nv_bfloat16 sm1[];
    __nv_bfloat16* As  = sm1;                  // [128][S1]  Y tile  [m][k]
    __nv_bfloat16* Was = sm1 + 128 * S1;       // [128][S1]  Wa rows [h][k]
    __nv_bfloat16* Wbs = Was + 128 * S1;       // [128][S1]  Wb rows
    int b = blockIdx.z;
    int h0 = blockIdx.y * 128;
    size_t m0 = (size_t)blockIdx.x * 128;
    int tid = threadIdx.x;

    const uint4* ysrc = (const uint4*)(g_Y + ((size_t)b * MDIM + m0) * CDIM);
    for (int i = tid; i < 128 * 16; i += 512) {      // 16 uint4 per 128-elem row
        int m = i >> 4, q = i & 15;
        *((uint4*)(As + m * S1) + q) = ysrc[m * 16 + q];
    }
    const uint4* wa = (const uint4*)(g_W1 + h0 * CDIM);
    const uint4* wb = (const uint4*)(g_W1 + (HDIM + h0) * CDIM);
    for (int i = tid; i < 128 * 16; i += 512) {
        int hh = i >> 4, q = i & 15;
        *((uint4*)(Was + hh * S1) + q) = wa[hh * 16 + q];
        *((uint4*)(Wbs + hh * S1) + q) = wb[hh * 16 + q];
    }
    __syncthreads();

    int wid = tid >> 5, lane = tid & 31;
    int wm = wid & 3, wn = wid >> 2;          // m offset wm*32, n offset wn*32
    int gid = lane >> 2, tg = lane & 3;

    unsigned aB[2], waB[2], wbB[2];
    {
        int arow = (lane & 15), akoff = (lane >> 4) * 8;
#pragma unroll
        for (int mt = 0; mt < 2; mt++)
            aB[mt] = sptr(As + (wm * 32 + mt * 16 + arow) * S1 + akoff);
        int brow = ((lane >> 4) << 3) + (lane & 7), bkoff = ((lane >> 3) & 1) * 8;
#pragma unroll
        for (int p = 0; p < 2; p++) {
            int n0 = wn * 32 + p * 16;
            waB[p] = sptr(Was + (n0 + brow) * S1 + bkoff);
            wbB[p] = sptr(Wbs + (n0 + brow) * S1 + bkoff);
        }
    }

    float accA[2][4][4], accB[2][4][4];
#pragma unroll
    for (int i = 0; i < 2; i++)
#pragma unroll
        for (int j = 0; j < 4; j++)
#pragma unroll
            for (int r = 0; r < 4; r++) { accA[i][j][r] = 0.f; accB[i][j][r] = 0.f; }

#pragma unroll
    for (int kk = 0; kk < 128; kk += 16) {
        unsigned afr[2][4], waf[2][4], wbf[2][4];
        ldsm4(aB[0] + kk * 2, afr[0]);
        ldsm4(aB[1] + kk * 2, afr[1]);
        ldsm4(waB[0] + kk * 2, waf[0]);
        ldsm4(waB[1] + kk * 2, waf[1]);
        ldsm4(wbB[0] + kk * 2, wbf[0]);
        ldsm4(wbB[1] + kk * 2, wbf[1]);
#pragma unroll
        for (int nt = 0; nt < 4; nt++) {
            const unsigned* bA = &waf[nt >> 1][(nt & 1) * 2];
            const unsigned* bB = &wbf[nt >> 1][(nt & 1) * 2];
#pragma unroll
            for (int mt = 0; mt < 2; mt++) {
                mma16816(accA[mt][nt], afr[mt], bA);
                mma16816(accB[mt][nt], afr[mt], bB);
            }
        }
    }

#pragma unroll
    for (int mt = 0; mt < 2; mt++) {
#pragma unroll
        for (int nt = 0; nt < 4; nt++) {
            int hg = h0 + wn * 32 + nt * 8 + tg * 2;
            float bi0 = b_in[hg],        bi1 = b_in[hg + 1];
            float bg0 = b_in[HDIM + hg], bg1 = b_in[HDIM + hg + 1];
#pragma unroll
            for (int r = 0; r < 2; r++) {
                size_t m = m0 + wm * 32 + mt * 16 + gid + r * 8;
                float a0 = accA[mt][nt][r * 2 + 0] + bi0;
                float a1 = accA[mt][nt][r * 2 + 1] + bi1;
                float g0 = accB[mt][nt][r * 2 + 0] + bg0;
                float g1 = accB[mt][nt][r * 2 + 1] + bg1;
                float u0 = a0 / (1.f + __expf(-g0));
                float u1 = a1 / (1.f + __expf(-g1));
                *(__nv_bfloat162*)(g_U + ((size_t)b * MDIM + m) * HDIM + hg) =
                    __floats2bfloat162_rn(u0, u1);
            }
        }
    }
}

// ---------------- kernel 3: FUSED depthwise 3x3 + SiLU + GEMM2 + residual ----
// Block = one (f, t0..t0+127) strip => computes out[b][:][f][t0..t0+127].
// Phase A: 4 chunks of 32 t: stage U halo [3][34][256] in smem, sliding-window
//          dw-conv + SiLU, write V tile straight into the GEMM As buffer.
// Phase B: 128x128 GEMM over K=256 with residual epilogue. g_V eliminated.
#define S2 264
#define DWC 32
#define USZ (3 * (DWC + 2) * HDIM)     /* 26112 elems */
__device__ __forceinline__ void ld4sm(const __nv_bfloat16* p, float* o) {
    uint2 v = *(const uint2*)p;
    float2 f0 = __bfloat1622float2(*(__nv_bfloat162*)&v.x);
    float2 f1 = __bfloat1622float2(*(__nv_bfloat162*)&v.y);
    o[0] = f0.x; o[1] = f0.y; o[2] = f1.x; o[3] = f1.y;
}
__global__ __launch_bounds__(256, 1) void k_dwg2(const float* __restrict__ w_dw,
                                                 const float* __restrict__ b_dw,
                                                 const float* __restrict__ x,
                                                 const float* __restrict__ b_out,
                                                 float* __restrict__ out) {
    extern __shared__ __nv_bfloat16 sm2[];
    __nv_bfloat16* As = sm2;                    // [128][S2]  V tile [m][h]
    __nv_bfloat16* Ws = sm2 + 128 * S2;         // [128][S2]  w_out  [c][h]
    __nv_bfloat16* Us = sm2 + 256 * S2;         // [3][34][HDIM] U halo stage
    int tid = threadIdx.x;
    int b = blockIdx.z, f = blockIdx.y, t0 = blockIdx.x * 128;

    // ---- weights for GEMM (global, once) ----
    const uint4* wsrc = (const uint4*)g_W2;
    for (int i = tid; i < 128 * 32; i += 256) {
        int c = i >> 5, q = i & 31;
        *((uint4*)(Ws + c * S2) + q) = wsrc[c * 32 + q];
    }

    // ---- per-thread dw params ----
    int h4 = (tid & 63) * 4;
    int tseg = tid >> 6;                 // 0..3, 8 t-steps each per chunk
    float wd[4][9], bd[4];
#pragma unroll
    for (int j = 0; j < 4; j++) {
#pragma unroll
        for (int i = 0; i < 9; i++) wd[j][i] = w_dw[(h4 + j) * 9 + i];
        bd[j] = b_dw[h4 + j];
    }

    const size_t HT = (size_t)TDIM * HDIM;
    const __nv_bfloat16* ub = g_U + (size_t)b * MDIM * HDIM;

    // ---- Phase A: 4 chunks of 32 t ----
    for (int ch = 0; ch < 4; ch++) {
        int tc0 = t0 + ch * DWC;
        __syncthreads();   // prev chunk's compute done before overwriting Us
        // stage [3][34][256]: 3264 uint4 over 256 threads
        for (int i = tid; i < 3 * (DWC + 2) * 32; i += 256) {
            int r = i / ((DWC + 2) * 32);
            int rem = i - r * ((DWC + 2) * 32);
            int tt = rem >> 5, q = rem & 31;
            int ff = f - 1 + r, t = tc0 - 2 + tt;
            uint4 v = make_uint4(0u, 0u, 0u, 0u);
            if (ff >= 0 && ff < FDIM && t >= 0)
                v = *(const uint4*)(ub + (size_t)ff * HT + (size_t)t * HDIM + q * 8);
            *((uint4*)(Us + (r * (DWC + 2) + tt) * HDIM) + q) = v;
        }
        __syncthreads();

        int lt = tseg * 8;   // local t window start within chunk
        float a0[3][4], a1[3][4];
#pragma unroll
        for (int r = 0; r < 3; r++) {
            ld4sm(Us + (r * (DWC + 2) + lt) * HDIM + h4, a0[r]);
            ld4sm(Us + (r * (DWC + 2) + lt + 1) * HDIM + h4, a1[r]);
        }
#pragma unroll
        for (int j = 0; j < 8; j++) {
            float cur[3][4];
#pragma unroll
            for (int r = 0; r < 3; r++)
                ld4sm(Us + (r * (DWC + 2) + lt + 2 + j) * HDIM + h4, cur[r]);
            float res[4];
#pragma unroll
            for (int q = 0; q < 4; q++) {
                float acc = bd[q];
                acc += a0[0][q] * wd[q][0] + a1[0][q] * wd[q][1] + cur[0][q] * wd[q][2];
                acc += a0[1][q] * wd[q][3] + a1[1][q] * wd[q][4] + cur[1][q] * wd[q][5];
                acc += a0[2][q] * wd[q][6] + a1[2][q] * wd[q][7] + cur[2][q] * wd[q][8];
                res[q] = acc / (1.f + __expf(-acc));
            }
            int row = ch * DWC + lt + j;     // m within tile
            uint2 pk;
            __nv_bfloat162 p0 = __floats2bfloat162_rn(res[0], res[1]);
            __nv_bfloat162 p1 = __floats2bfloat162_rn(res[2], res[3]);
            pk.x = *(unsigned*)&p0; pk.y = *(unsigned*)&p1;
            *(uint2*)(As + row * S2 + h4) = pk;
#pragma unroll
            for (int r = 0; r < 3; r++)
#pragma unroll
                for (int q = 0; q < 4; q++) { a0[r][q] = a1[r][q]; a1[r][q] = cur[r][q]; }
        }
    }
    __syncthreads();

    // ---- Phase B: GEMM 128m x 128c, K=256 ----
    size_t m0 = (size_t)f * TDIM + t0;
    int wid = tid >> 5, lane = tid & 31;
    int wm = wid & 3, wn = wid >> 2;       // m offset wm*32, c offset wn*64
    int gid = lane >> 2, tg = lane & 3;

    unsigned aB[2], wB[4];
    {
        int arow = (lane & 15), akoff = (lane >> 4) * 8;
#pragma unroll
        for (int mt = 0; mt < 2; mt++)
            aB[mt] = sptr(As + (wm * 32 + mt * 16 + arow) * S2 + akoff);
        int brow = ((lane >> 4) << 3) + (lane & 7), bkoff = ((lane >> 3) & 1) * 8;
#pragma unroll
        for (int p = 0; p < 4; p++) {
            int n0 = wn * 64 + p * 16;
            wB[p] = sptr(Ws + (n0 + brow) * S2 + bkoff);
        }
    }

    float acc[2][8][4];
#pragma unroll
    for (int i = 0; i < 2; i++)
#pragma unroll
        for (int j = 0; j < 8; j++)
#pragma unroll
            for (int r = 0; r < 4; r++) acc[i][j][r] = 0.f;

#pragma unroll 4
    for (int kk = 0; kk < 256; kk += 16) {
        unsigned afr[2][4], bfr[4][4];
        ldsm4(aB[0] + kk * 2, afr[0]);
        ldsm4(aB[1] + kk * 2, afr[1]);
#pragma unroll
        for (int p = 0; p < 4; p++) ldsm4(wB[p] + kk * 2, bfr[p]);
#pragma unroll
        for (int nt = 0; nt < 8; nt++) {
            const unsigned* bb = &bfr[nt >> 1][(nt & 1) * 2];
#pragma unroll
            for (int mt = 0; mt < 2; mt++) mma16816(acc[mt][nt], afr[mt], bb);
        }
    }

    // epilogue: out[b][c][m] = x + acc + b_out[c]
#pragma unroll
    for (int mt = 0; mt < 2; mt++) {
#pragma unroll
        for (int nt = 0; nt < 8; nt++) {
            int c = wn * 64 + nt * 8 + tg * 2;
            float bo0 = b_out[c], bo1 = b_out[c + 1];
#pragma unroll
            for (int r = 0; r < 2; r++) {
                size_t m = m0 + wm * 32 + mt * 16 + gid + r * 8;
                size_t i0 = ((size_t)(b * CDIM + c)) * MDIM + m;
                size_t i1 = i0 + MDIM;
                out[i0] = x[i0] + acc[mt][nt][r * 2 + 0] + bo0;
                out[i1] = x[i1] + acc[mt][nt][r * 2 + 1] + bo1;
            }
        }
    }
}

// ---------------- launch ------------------------------------------------------
extern "C" void kernel_launch(void* const* d_in, const int* in_sizes, int n_in,
                              void* d_out, int out_size) {
    const float* x      = (const float*)d_in[0];
    const float* g_norm = (const float*)d_in[1];
    const float* w_in   = (const float*)d_in[2];
    const float* b_in   = (const float*)d_in[3];
    const float* w_dw   = (const float*)d_in[4];
    const float* b_dw   = (const float*)d_in[5];
    const float* w_out  = (const float*)d_in[6];
    const float* b_out  = (const float*)d_in[7];
    float* out = (float*)d_out;

    const int smem1 = 384 * S1 * (int)sizeof(__nv_bfloat16);          // 104448
    const int smem2 = (256 * S2 + USZ) * (int)sizeof(__nv_bfloat16);  // 187392
    cudaFuncSetAttribute(k_gemm1, cudaFuncAttributeMaxDynamicSharedMemorySize, smem1);
    cudaFuncSetAttribute(k_dwg2,  cudaFuncAttributeMaxDynamicSharedMemorySize, smem2);

    k_prep<<<256, 256>>>(w_in, g_norm, w_out);
    k_rms<<<dim3(TDIM / 64, FDIM, BATCH), 256>>>(x, g_norm);
    k_gemm1<<<dim3(MDIM / 128, HDIM / 128, BATCH), 512, smem1>>>(b_in);
    k_dwg2<<<dim3(TDIM / 128, FDIM, BATCH), 256, smem2>>>(w_dw, b_dw, x, b_out, out);
}

// round 5
// speedup vs baseline: 1.1771x; 1.0038x over previous
#include <cuda_runtime.h>
#include <cuda_bf16.h>

#define BATCH 4
#define CDIM 128
#define FDIM 128
#define TDIM 512
#define HDIM 256
#define MDIM (FDIM*TDIM)   /* 65536 positions per batch */
#define EPSV 1e-6f

// ---------------- scratch (static device globals; no runtime alloc) ----------
__device__ __nv_bfloat16 g_Y[(size_t)BATCH * MDIM * CDIM];   //  64 MB  [b][m][c]
__device__ __nv_bfloat16 g_U[(size_t)BATCH * MDIM * HDIM];   // 128 MB  [b][m][h]
__device__ __nv_bfloat16 g_W1[2 * HDIM * CDIM];              // w_in * g_norm (bf16)
__device__ __nv_bfloat16 g_W2[CDIM * HDIM];                  // w_out (bf16)

// ---------------- kernel 0: weight prep --------------------------------------
__global__ void k_prep(const float* __restrict__ w_in,
                       const float* __restrict__ gn,
                       const float* __restrict__ w_out) {
    int i = blockIdx.x * 256 + threadIdx.x;
    if (i < 2 * HDIM * CDIM)
        g_W1[i] = __float2bfloat16(w_in[i] * gn[i & (CDIM - 1)]);
    if (i < CDIM * HDIM)
        g_W2[i] = __float2bfloat16(w_out[i]);
}

// ---------------- kernel 1: RMSNorm + transpose to [m][c] bf16 ---------------
__global__ __launch_bounds__(256) void k_rms(const float* __restrict__ x,
                                             const float* __restrict__ gn) {
    __shared__ float xs[CDIM][65];   // [c][t] padded
    __shared__ float ps[4][64];
    __shared__ float ssc[64];
    __shared__ float gs[CDIM];
    int b = blockIdx.z, f = blockIdx.y, t0 = blockIdx.x * 64;
    int tid = threadIdx.x;
    const float* xb = x + ((size_t)(b * CDIM) * FDIM + f) * TDIM + t0;
    for (int i = tid; i < CDIM * 64; i += 256) {
        int c = i >> 6, t = i & 63;
        xs[c][t] = xb[(size_t)c * FDIM * TDIM + t];
    }
    if (tid < CDIM) gs[tid] = gn[tid];
    __syncthreads();
    {
        int t = tid & 63, cs = (tid >> 6) * 32;
        float s = 0.f;
#pragma unroll
        for (int c = 0; c < 32; c++) { float v = xs[cs + c][t]; s += v * v; }
        ps[tid >> 6][t] = s;
    }
    __syncthreads();
    if (tid < 64) {
        float s = ps[0][tid] + ps[1][tid] + ps[2][tid] + ps[3][tid];
        ssc[tid] = rsqrtf(s * (1.0f / CDIM) + EPSV);
    }
    __syncthreads();
    __nv_bfloat16* yb = g_Y + ((size_t)b * MDIM + (size_t)f * TDIM + t0) * CDIM;
    for (int i = tid; i < 64 * CDIM; i += 256) {
        int t = i >> 7, c = i & 127;
        yb[(size_t)t * CDIM + c] = __float2bfloat16(xs[c][t] * ssc[t] * gs[c]);
    }
}

// ---------------- mma / ldmatrix helpers --------------------------------------
__device__ __forceinline__ void mma16816(float* d, const unsigned* a, const unsigned* bb) {
    asm volatile(
        "mma.sync.aligned.m16n8k16.row.col.f32.bf16.bf16.f32 "
        "{%0,%1,%2,%3},{%4,%5,%6,%7},{%8,%9},{%0,%1,%2,%3};\n"
        : "+f"(d[0]), "+f"(d[1]), "+f"(d[2]), "+f"(d[3])
        : "r"(a[0]), "r"(a[1]), "r"(a[2]), "r"(a[3]), "r"(bb[0]), "r"(bb[1]));
}
__device__ __forceinline__ unsigned sptr(const void* p) {
    unsigned r;
    asm("{.reg .u64 t; cvta.to.shared.u64 t, %1; cvt.u32.u64 %0, t;}" : "=r"(r) : "l"(p));
    return r;
}
__device__ __forceinline__ void ldsm4(unsigned addr, unsigned* r) {
    asm volatile("ldmatrix.sync.aligned.m8n8.x4.shared.b16 {%0,%1,%2,%3},[%4];"
                 : "=r"(r[0]), "=r"(r[1]), "=r"(r[2]), "=r"(r[3]) : "r"(addr));
}

// ---------------- kernel 2: GEMM1 (512x128 weights) + bias + GLU -------------
#define S1 136   // smem row stride (elems)
__global__ __launch_bounds__(512, 1) void k_gemm1(const float* __restrict__ b_in) {
    extern __shared__ __nv_bfloat16 sm1[];
    __nv_bfloat16* As  = sm1;                  // [128][S1]  Y tile  [m][k]
    __nv_bfloat16* Was = sm1 + 128 * S1;       // [128][S1]  Wa rows [h][k]
    __nv_bfloat16* Wbs = Was + 128 * S1;       // [128][S1]  Wb rows
    int b = blockIdx.z;
    int h0 = blockIdx.y * 128;
    size_t m0 = (size_t)blockIdx.x * 128;
    int tid = threadIdx.x;

    const uint4* ysrc = (const uint4*)(g_Y + ((size_t)b * MDIM + m0) * CDIM);
    for (int i = tid; i < 128 * 16; i += 512) {
        int m = i >> 4, q = i & 15;
        *((uint4*)(As + m * S1) + q) = ysrc[m * 16 + q];
    }
    const uint4* wa = (const uint4*)(g_W1 + h0 * CDIM);
    const uint4* wb = (const uint4*)(g_W1 + (HDIM + h0) * CDIM);
    for (int i = tid; i < 128 * 16; i += 512) {
        int hh = i >> 4, q = i & 15;
        *((uint4*)(Was + hh * S1) + q) = wa[hh * 16 + q];
        *((uint4*)(Wbs + hh * S1) + q) = wb[hh * 16 + q];
    }
    __syncthreads();

    int wid = tid >> 5, lane = tid & 31;
    int wm = wid & 3, wn = wid >> 2;
    int gid = lane >> 2, tg = lane & 3;

    unsigned aB[2], waB[2], wbB[2];
    {
        int arow = (lane & 15), akoff = (lane >> 4) * 8;
#pragma unroll
        for (int mt = 0; mt < 2; mt++)
            aB[mt] = sptr(As + (wm * 32 + mt * 16 + arow) * S1 + akoff);
        int brow = ((lane >> 4) << 3) + (lane & 7), bkoff = ((lane >> 3) & 1) * 8;
#pragma unroll
        for (int p = 0; p < 2; p++) {
            int n0 = wn * 32 + p * 16;
            waB[p] = sptr(Was + (n0 + brow) * S1 + bkoff);
            wbB[p] = sptr(Wbs + (n0 + brow) * S1 + bkoff);
        }
    }

    float accA[2][4][4], accB[2][4][4];
#pragma unroll
    for (int i = 0; i < 2; i++)
#pragma unroll
        for (int j = 0; j < 4; j++)
#pragma unroll
            for (int r = 0; r < 4; r++) { accA[i][j][r] = 0.f; accB[i][j][r] = 0.f; }

#pragma unroll
    for (int kk = 0; kk < 128; kk += 16) {
        unsigned afr[2][4], waf[2][4], wbf[2][4];
        ldsm4(aB[0] + kk * 2, afr[0]);
        ldsm4(aB[1] + kk * 2, afr[1]);
        ldsm4(waB[0] + kk * 2, waf[0]);
        ldsm4(waB[1] + kk * 2, waf[1]);
        ldsm4(wbB[0] + kk * 2, wbf[0]);
        ldsm4(wbB[1] + kk * 2, wbf[1]);
#pragma unroll
        for (int nt = 0; nt < 4; nt++) {
            const unsigned* bA = &waf[nt >> 1][(nt & 1) * 2];
            const unsigned* bB = &wbf[nt >> 1][(nt & 1) * 2];
#pragma unroll
            for (int mt = 0; mt < 2; mt++) {
                mma16816(accA[mt][nt], afr[mt], bA);
                mma16816(accB[mt][nt], afr[mt], bB);
            }
        }
    }

#pragma unroll
    for (int mt = 0; mt < 2; mt++) {
#pragma unroll
        for (int nt = 0; nt < 4; nt++) {
            int hg = h0 + wn * 32 + nt * 8 + tg * 2;
            float bi0 = b_in[hg],        bi1 = b_in[hg + 1];
            float bg0 = b_in[HDIM + hg], bg1 = b_in[HDIM + hg + 1];
#pragma unroll
            for (int r = 0; r < 2; r++) {
                size_t m = m0 + wm * 32 + mt * 16 + gid + r * 8;
                float a0 = accA[mt][nt][r * 2 + 0] + bi0;
                float a1 = accA[mt][nt][r * 2 + 1] + bi1;
                float g0 = accB[mt][nt][r * 2 + 0] + bg0;
                float g1 = accB[mt][nt][r * 2 + 1] + bg1;
                float u0 = a0 / (1.f + __expf(-g0));
                float u1 = a1 / (1.f + __expf(-g1));
                *(__nv_bfloat162*)(g_U + ((size_t)b * MDIM + m) * HDIM + hg) =
                    __floats2bfloat162_rn(u0, u1);
            }
        }
    }
}

// ---------------- kernel 3: FUSED depthwise 3x3 + SiLU + GEMM2 + residual ----
// 512 threads. Block = one (f, t0..t0+127) strip.
// Phase A: 4 chunks of 32 t: stage U halo [3][34][256], sliding-window dw+SiLU,
//          write V straight into GEMM As buffer.
// Phase B: GEMM with A = w_out (c = M dim), B = V (m = N dim)  => epilogue
//          stores are contiguous along m (fully coalesced out/x traffic).
#define S2 264
#define DWC 32
#define USZ (3 * (DWC + 2) * HDIM)     /* 26112 elems */
__device__ __forceinline__ void ld4sm(const __nv_bfloat16* p, float* o) {
    uint2 v = *(const uint2*)p;
    float2 f0 = __bfloat1622float2(*(__nv_bfloat162*)&v.x);
    float2 f1 = __bfloat1622float2(*(__nv_bfloat162*)&v.y);
    o[0] = f0.x; o[1] = f0.y; o[2] = f1.x; o[3] = f1.y;
}
__global__ __launch_bounds__(512, 1) void k_dwg2(const float* __restrict__ w_dw,
                                                 const float* __restrict__ b_dw,
                                                 const float* __restrict__ x,
                                                 const float* __restrict__ b_out,
                                                 float* __restrict__ out) {
    extern __shared__ __nv_bfloat16 sm2[];
    __nv_bfloat16* As = sm2;                    // [128 m][S2]  V tile
    __nv_bfloat16* Ws = sm2 + 128 * S2;         // [128 c][S2]  w_out
    __nv_bfloat16* Us = sm2 + 256 * S2;         // [3][34][HDIM] U halo stage
    int tid = threadIdx.x;
    int b = blockIdx.z, f = blockIdx.y, t0 = blockIdx.x * 128;

    // ---- weights for GEMM ----
    const uint4* wsrc = (const uint4*)g_W2;
    for (int i = tid; i < 128 * 32; i += 512) {
        int c = i >> 5, q = i & 31;
        *((uint4*)(Ws + c * S2) + q) = wsrc[c * 32 + q];
    }

    // ---- per-thread dw params: 4 h-channels, 4 t-steps per chunk ----
    int h4 = (tid & 63) * 4;
    int tseg = tid >> 6;                 // 0..7
    float wd[4][9], bd[4];
#pragma unroll
    for (int j = 0; j < 4; j++) {
#pragma unroll
        for (int i = 0; i < 9; i++) wd[j][i] = w_dw[(h4 + j) * 9 + i];
        bd[j] = b_dw[h4 + j];
    }

    const size_t HT = (size_t)TDIM * HDIM;
    const __nv_bfloat16* ub = g_U + (size_t)b * MDIM * HDIM;

    // ---- Phase A: 4 chunks of 32 t ----
    for (int ch = 0; ch < 4; ch++) {
        int tc0 = t0 + ch * DWC;
        __syncthreads();
        for (int i = tid; i < 3 * (DWC + 2) * 32; i += 512) {
            int r = i / ((DWC + 2) * 32);
            int rem = i - r * ((DWC + 2) * 32);
            int tt = rem >> 5, q = rem & 31;
            int ff = f - 1 + r, t = tc0 - 2 + tt;
            uint4 v = make_uint4(0u, 0u, 0u, 0u);
            if (ff >= 0 && ff < FDIM && t >= 0)
                v = *(const uint4*)(ub + (size_t)ff * HT + (size_t)t * HDIM + q * 8);
            *((uint4*)(Us + (r * (DWC + 2) + tt) * HDIM) + q) = v;
        }
        __syncthreads();

        int lt = tseg * 4;   // local t window start within chunk
        float a0[3][4], a1[3][4];
#pragma unroll
        for (int r = 0; r < 3; r++) {
            ld4sm(Us + (r * (DWC + 2) + lt) * HDIM + h4, a0[r]);
            ld4sm(Us + (r * (DWC + 2) + lt + 1) * HDIM + h4, a1[r]);
        }
#pragma unroll
        for (int j = 0; j < 4; j++) {
            float cur[3][4];
#pragma unroll
            for (int r = 0; r < 3; r++)
                ld4sm(Us + (r * (DWC + 2) + lt + 2 + j) * HDIM + h4, cur[r]);
            float res[4];
#pragma unroll
            for (int q = 0; q < 4; q++) {
                float acc = bd[q];
                acc += a0[0][q] * wd[q][0] + a1[0][q] * wd[q][1] + cur[0][q] * wd[q][2];
                acc += a0[1][q] * wd[q][3] + a1[1][q] * wd[q][4] + cur[1][q] * wd[q][5];
                acc += a0[2][q] * wd[q][6] + a1[2][q] * wd[q][7] + cur[2][q] * wd[q][8];
                res[q] = acc / (1.f + __expf(-acc));
            }
            int row = ch * DWC + lt + j;     // m within tile
            uint2 pk;
            __nv_bfloat162 p0 = __floats2bfloat162_rn(res[0], res[1]);
            __nv_bfloat162 p1 = __floats2bfloat162_rn(res[2], res[3]);
            pk.x = *(unsigned*)&p0; pk.y = *(unsigned*)&p1;
            *(uint2*)(As + row * S2 + h4) = pk;
#pragma unroll
            for (int r = 0; r < 3; r++)
#pragma unroll
                for (int q = 0; q < 4; q++) { a0[r][q] = a1[r][q]; a1[r][q] = cur[r][q]; }
        }
    }
    __syncthreads();

    // ---- Phase B: GEMM. M dim = c (Ws rows), N dim = m (As rows). ----
    // 16 warps: wm = c-block (4 x 32c), wn = m-block (4 x 32m). Warp = 32c x 32m.
    size_t m0 = (size_t)f * TDIM + t0;
    int wid = tid >> 5, lane = tid & 31;
    int wm = wid >> 2, wn = wid & 3;
    int gid = lane >> 2, tg = lane & 3;

    unsigned aB[2], bB[2];
    {
        int arow = (lane & 15), akoff = (lane >> 4) * 8;
#pragma unroll
        for (int mt = 0; mt < 2; mt++)
            aB[mt] = sptr(Ws + (wm * 32 + mt * 16 + arow) * S2 + akoff);
        int brow = ((lane >> 4) << 3) + (lane & 7), bkoff = ((lane >> 3) & 1) * 8;
#pragma unroll
        for (int p = 0; p < 2; p++)
            bB[p] = sptr(As + (wn * 32 + p * 16 + brow) * S2 + bkoff);
    }

    float acc[2][4][4];
#pragma unroll
    for (int i = 0; i < 2; i++)
#pragma unroll
        for (int j = 0; j < 4; j++)
#pragma unroll
            for (int r = 0; r < 4; r++) acc[i][j][r] = 0.f;

#pragma unroll 4
    for (int kk = 0; kk < 256; kk += 16) {
        unsigned afr[2][4], bfr[2][4];
        ldsm4(aB[0] + kk * 2, afr[0]);
        ldsm4(aB[1] + kk * 2, afr[1]);
        ldsm4(bB[0] + kk * 2, bfr[0]);
        ldsm4(bB[1] + kk * 2, bfr[1]);
#pragma unroll
        for (int nt = 0; nt < 4; nt++) {
            const unsigned* bb = &bfr[nt >> 1][(nt & 1) * 2];
#pragma unroll
            for (int mt = 0; mt < 2; mt++) mma16816(acc[mt][nt], afr[mt], bb);
        }
    }

    // epilogue: out[b][c][m] = x + acc + b_out[c]; m contiguous per lane quad.
#pragma unroll
    for (int mt = 0; mt < 2; mt++) {
#pragma unroll
        for (int nt = 0; nt < 4; nt++) {
            int ml = wn * 32 + nt * 8 + tg * 2;
#pragma unroll
            for (int r = 0; r < 2; r++) {
                int c = wm * 32 + mt * 16 + gid + r * 8;
                float bo = b_out[c];
                size_t idx = ((size_t)(b * CDIM + c)) * MDIM + m0 + ml;
                float2 xr = *(const float2*)(x + idx);
                float2 o;
                o.x = xr.x + acc[mt][nt][r * 2 + 0] + bo;
                o.y = xr.y + acc[mt][nt][r * 2 + 1] + bo;
                *(float2*)(out + idx) = o;
            }
        }
    }
}

// ---------------- launch ------------------------------------------------------
extern "C" void kernel_launch(void* const* d_in, const int* in_sizes, int n_in,
                              void* d_out, int out_size) {
    const float* x      = (const float*)d_in[0];
    const float* g_norm = (const float*)d_in[1];
    const float* w_in   = (const float*)d_in[2];
    const float* b_in   = (const float*)d_in[3];
    const float* w_dw   = (const float*)d_in[4];
    const float* b_dw   = (const float*)d_in[5];
    const float* w_out  = (const float*)d_in[6];
    const float* b_out  = (const float*)d_in[7];
    float* out = (float*)d_out;

    const int smem1 = 384 * S1 * (int)sizeof(__nv_bfloat16);          // 104448
    const int smem2 = (256 * S2 + USZ) * (int)sizeof(__nv_bfloat16);  // 187392
    cudaFuncSetAttribute(k_gemm1, cudaFuncAttributeMaxDynamicSharedMemorySize, smem1);
    cudaFuncSetAttribute(k_dwg2,  cudaFuncAttributeMaxDynamicSharedMemorySize, smem2);

    k_prep<<<256, 256>>>(w_in, g_norm, w_out);
    k_rms<<<dim3(TDIM / 64, FDIM, BATCH), 256>>>(x, g_norm);
    k_gemm1<<<dim3(MDIM / 128, HDIM / 128, BATCH), 512, smem1>>>(b_in);
    k_dwg2<<<dim3(TDIM / 128, FDIM, BATCH), 512, smem2>>>(w_dw, b_dw, x, b_out, out);
}

// round 6
// speedup vs baseline: 1.4288x; 1.2138x over previous
#include <cuda_runtime.h>
#include <cuda_bf16.h>

#define BATCH 4
#define CDIM 128
#define FDIM 128
#define TDIM 512
#define HDIM 256
#define MDIM (FDIM*TDIM)   /* 65536 positions per batch */
#define EPSV 1e-6f

// ---------------- scratch (static device globals; no runtime alloc) ----------
__device__ __nv_bfloat16 g_Y[(size_t)BATCH * MDIM * CDIM];   //  64 MB  [b][m][c]
__device__ __nv_bfloat16 g_U[(size_t)BATCH * MDIM * HDIM];   // 128 MB  [b][m][h]
__device__ __nv_bfloat16 g_V[(size_t)BATCH * MDIM * HDIM];   // 128 MB  [b][m][h]
__device__ __nv_bfloat16 g_W1[2 * HDIM * CDIM];              // w_in * g_norm (bf16)
__device__ __nv_bfloat16 g_W2[CDIM * HDIM];                  // w_out (bf16)

// ---------------- kernel 0: weight prep --------------------------------------
__global__ void k_prep(const float* __restrict__ w_in,
                       const float* __restrict__ gn,
                       const float* __restrict__ w_out) {
    int i = blockIdx.x * 256 + threadIdx.x;
    if (i < 2 * HDIM * CDIM)
        g_W1[i] = __float2bfloat16(w_in[i] * gn[i & (CDIM - 1)]);
    if (i < CDIM * HDIM)
        g_W2[i] = __float2bfloat16(w_out[i]);
}

// ---------------- kernel 1: RMSNorm + transpose to [m][c] bf16 ---------------
__global__ __launch_bounds__(256) void k_rms(const float* __restrict__ x,
                                             const float* __restrict__ gn) {
    __shared__ float xs[CDIM][65];   // [c][t] padded
    __shared__ float ps[4][64];
    __shared__ float ssc[64];
    __shared__ float gs[CDIM];
    int b = blockIdx.z, f = blockIdx.y, t0 = blockIdx.x * 64;
    int tid = threadIdx.x;
    const float* xb = x + ((size_t)(b * CDIM) * FDIM + f) * TDIM + t0;
    for (int i = tid; i < CDIM * 64; i += 256) {
        int c = i >> 6, t = i & 63;
        xs[c][t] = xb[(size_t)c * FDIM * TDIM + t];
    }
    if (tid < CDIM) gs[tid] = gn[tid];
    __syncthreads();
    {
        int t = tid & 63, cs = (tid >> 6) * 32;
        float s = 0.f;
#pragma unroll
        for (int c = 0; c < 32; c++) { float v = xs[cs + c][t]; s += v * v; }
        ps[tid >> 6][t] = s;
    }
    __syncthreads();
    if (tid < 64) {
        float s = ps[0][tid] + ps[1][tid] + ps[2][tid] + ps[3][tid];
        ssc[tid] = rsqrtf(s * (1.0f / CDIM) + EPSV);
    }
    __syncthreads();
    __nv_bfloat16* yb = g_Y + ((size_t)b * MDIM + (size_t)f * TDIM + t0) * CDIM;
    for (int i = tid; i < 64 * CDIM; i += 256) {
        int t = i >> 7, c = i & 127;
        yb[(size_t)t * CDIM + c] = __float2bfloat16(xs[c][t] * ssc[t] * gs[c]);
    }
}

// ---------------- mma / ldmatrix helpers --------------------------------------
__device__ __forceinline__ void mma16816(float* d, const unsigned* a, const unsigned* bb) {
    asm volatile(
        "mma.sync.aligned.m16n8k16.row.col.f32.bf16.bf16.f32 "
        "{%0,%1,%2,%3},{%4,%5,%6,%7},{%8,%9},{%0,%1,%2,%3};\n"
        : "+f"(d[0]), "+f"(d[1]), "+f"(d[2]), "+f"(d[3])
        : "r"(a[0]), "r"(a[1]), "r"(a[2]), "r"(a[3]), "r"(bb[0]), "r"(bb[1]));
}
__device__ __forceinline__ unsigned sptr(const void* p) {
    unsigned r;
    asm("{.reg .u64 t; cvta.to.shared.u64 t, %1; cvt.u32.u64 %0, t;}" : "=r"(r) : "l"(p));
    return r;
}
__device__ __forceinline__ void ldsm4(unsigned addr, unsigned* r) {
    asm volatile("ldmatrix.sync.aligned.m8n8.x4.shared.b16 {%0,%1,%2,%3},[%4];"
                 : "=r"(r[0]), "=r"(r[1]), "=r"(r[2]), "=r"(r[3]) : "r"(addr));
}

// ---------------- kernel 2: GEMM1 (512x128 weights) + bias + GLU -------------
#define S1 136   // smem row stride (elems)
__global__ __launch_bounds__(512, 1) void k_gemm1(const float* __restrict__ b_in) {
    extern __shared__ __nv_bfloat16 sm1[];
    __nv_bfloat16* As  = sm1;                  // [128][S1]  Y tile  [m][k]
    __nv_bfloat16* Was = sm1 + 128 * S1;       // [128][S1]  Wa rows [h][k]
    __nv_bfloat16* Wbs = Was + 128 * S1;       // [128][S1]  Wb rows
    int b = blockIdx.z;
    int h0 = blockIdx.y * 128;
    size_t m0 = (size_t)blockIdx.x * 128;
    int tid = threadIdx.x;

    const uint4* ysrc = (const uint4*)(g_Y + ((size_t)b * MDIM + m0) * CDIM);
    for (int i = tid; i < 128 * 16; i += 512) {
        int m = i >> 4, q = i & 15;
        *((uint4*)(As + m * S1) + q) = ysrc[m * 16 + q];
    }
    const uint4* wa = (const uint4*)(g_W1 + h0 * CDIM);
    const uint4* wb = (const uint4*)(g_W1 + (HDIM + h0) * CDIM);
    for (int i = tid; i < 128 * 16; i += 512) {
        int hh = i >> 4, q = i & 15;
        *((uint4*)(Was + hh * S1) + q) = wa[hh * 16 + q];
        *((uint4*)(Wbs + hh * S1) + q) = wb[hh * 16 + q];
    }
    __syncthreads();

    int wid = tid >> 5, lane = tid & 31;
    int wm = wid & 3, wn = wid >> 2;
    int gid = lane >> 2, tg = lane & 3;

    unsigned aB[2], waB[2], wbB[2];
    {
        int arow = (lane & 15), akoff = (lane >> 4) * 8;
#pragma unroll
        for (int mt = 0; mt < 2; mt++)
            aB[mt] = sptr(As + (wm * 32 + mt * 16 + arow) * S1 + akoff);
        int brow = ((lane >> 4) << 3) + (lane & 7), bkoff = ((lane >> 3) & 1) * 8;
#pragma unroll
        for (int p = 0; p < 2; p++) {
            int n0 = wn * 32 + p * 16;
            waB[p] = sptr(Was + (n0 + brow) * S1 + bkoff);
            wbB[p] = sptr(Wbs + (n0 + brow) * S1 + bkoff);
        }
    }

    float accA[2][4][4], accB[2][4][4];
#pragma unroll
    for (int i = 0; i < 2; i++)
#pragma unroll
        for (int j = 0; j < 4; j++)
#pragma unroll
            for (int r = 0; r < 4; r++) { accA[i][j][r] = 0.f; accB[i][j][r] = 0.f; }

#pragma unroll
    for (int kk = 0; kk < 128; kk += 16) {
        unsigned afr[2][4], waf[2][4], wbf[2][4];
        ldsm4(aB[0] + kk * 2, afr[0]);
        ldsm4(aB[1] + kk * 2, afr[1]);
        ldsm4(waB[0] + kk * 2, waf[0]);
        ldsm4(waB[1] + kk * 2, waf[1]);
        ldsm4(wbB[0] + kk * 2, wbf[0]);
        ldsm4(wbB[1] + kk * 2, wbf[1]);
#pragma unroll
        for (int nt = 0; nt < 4; nt++) {
            const unsigned* bA = &waf[nt >> 1][(nt & 1) * 2];
            const unsigned* bB = &wbf[nt >> 1][(nt & 1) * 2];
#pragma unroll
            for (int mt = 0; mt < 2; mt++) {
                mma16816(accA[mt][nt], afr[mt], bA);
                mma16816(accB[mt][nt], afr[mt], bB);
            }
        }
    }

#pragma unroll
    for (int mt = 0; mt < 2; mt++) {
#pragma unroll
        for (int nt = 0; nt < 4; nt++) {
            int hg = h0 + wn * 32 + nt * 8 + tg * 2;
            float bi0 = b_in[hg],        bi1 = b_in[hg + 1];
            float bg0 = b_in[HDIM + hg], bg1 = b_in[HDIM + hg + 1];
#pragma unroll
            for (int r = 0; r < 2; r++) {
                size_t m = m0 + wm * 32 + mt * 16 + gid + r * 8;
                float a0 = accA[mt][nt][r * 2 + 0] + bi0;
                float a1 = accA[mt][nt][r * 2 + 1] + bi1;
                float g0 = accB[mt][nt][r * 2 + 0] + bg0;
                float g1 = accB[mt][nt][r * 2 + 1] + bg1;
                float u0 = a0 / (1.f + __expf(-g0));
                float u1 = a1 / (1.f + __expf(-g1));
                *(__nv_bfloat162*)(g_U + ((size_t)b * MDIM + m) * HDIM + hg) =
                    __floats2bfloat162_rn(u0, u1);
            }
        }
    }
}

// ---------------- kernel 3: depthwise 3x3 + SiLU (high occupancy) ------------
// One 32-t chunk per 256-thread CTA. smem 52KB => 4 CTAs/SM. 2 h per thread
// (low regs), register sliding window fed from zero-padded smem halo.
#define DWC 32
#define DWSM (3 * (DWC + 2) * HDIM)    /* 26112 elems = 52224 B */
__device__ __forceinline__ void ld2bf(const __nv_bfloat16* p, float* o) {
    float2 v = __bfloat1622float2(*(const __nv_bfloat162*)p);
    o[0] = v.x; o[1] = v.y;
}
__global__ __launch_bounds__(256, 4) void k_dw(const float* __restrict__ w_dw,
                                               const float* __restrict__ b_dw) {
    extern __shared__ __nv_bfloat16 Us[];   // [3][34][HDIM]
    int tid = threadIdx.x;
    int b = blockIdx.z, f = blockIdx.y, t0 = blockIdx.x * DWC;

    // ---- stage U halo [3][34][256] bf16, zero-filled edges ----
    const size_t HT = (size_t)TDIM * HDIM;
    const __nv_bfloat16* ub = g_U + (size_t)b * MDIM * HDIM;
#pragma unroll
    for (int i = tid; i < 3 * (DWC + 2) * 32; i += 256) {
        int r = i / ((DWC + 2) * 32);
        int rem = i - r * ((DWC + 2) * 32);
        int tt = rem >> 5, q = rem & 31;
        int ff = f - 1 + r, t = t0 - 2 + tt;
        uint4 v = make_uint4(0u, 0u, 0u, 0u);
        if (ff >= 0 && ff < FDIM && t >= 0)
            v = *(const uint4*)(ub + (size_t)ff * HT + (size_t)t * HDIM + q * 8);
        *((uint4*)(Us + (r * (DWC + 2) + tt) * HDIM) + q) = v;
    }
    __syncthreads();

    // ---- per-thread: 2 h-channels x 16 t-steps ----
    int hg = (tid & 127) * 2;
    int lt = (tid >> 7) * 16;        // 0 or 16

    float wd[2][9], bd[2];
#pragma unroll
    for (int j = 0; j < 2; j++) {
#pragma unroll
        for (int i = 0; i < 9; i++) wd[j][i] = w_dw[(hg + j) * 9 + i];
        bd[j] = b_dw[hg + j];
    }

    float a0[3][2], a1[3][2];
#pragma unroll
    for (int r = 0; r < 3; r++) {
        ld2bf(Us + (r * (DWC + 2) + lt) * HDIM + hg, a0[r]);
        ld2bf(Us + (r * (DWC + 2) + lt + 1) * HDIM + hg, a1[r]);
    }

    __nv_bfloat16* vout = g_V + ((size_t)b * MDIM + (size_t)f * TDIM + t0 + lt) * HDIM + hg;
#pragma unroll
    for (int j = 0; j < 16; j++) {
        float cur[3][2];
#pragma unroll
        for (int r = 0; r < 3; r++)
            ld2bf(Us + (r * (DWC + 2) + lt + 2 + j) * HDIM + hg, cur[r]);
        float res[2];
#pragma unroll
        for (int q = 0; q < 2; q++) {
            float acc = bd[q];
            acc += a0[0][q] * wd[q][0] + a1[0][q] * wd[q][1] + cur[0][q] * wd[q][2];
            acc += a0[1][q] * wd[q][3] + a1[1][q] * wd[q][4] + cur[1][q] * wd[q][5];
            acc += a0[2][q] * wd[q][6] + a1[2][q] * wd[q][7] + cur[2][q] * wd[q][8];
            res[q] = acc / (1.f + __expf(-acc));
        }
        *(__nv_bfloat162*)vout = __floats2bfloat162_rn(res[0], res[1]);
        vout += HDIM;
#pragma unroll
        for (int r = 0; r < 3; r++)
#pragma unroll
            for (int q = 0; q < 2; q++) { a0[r][q] = a1[r][q]; a1[r][q] = cur[r][q]; }
    }
}

// ---------------- kernel 4: GEMM2 (128c x 64m, K=256) + residual -------------
// A = w_out (c = M dim), B = V (m = N dim). smem 101.4KB => 2 CTAs/SM.
// Epilogue contiguous along m (coalesced out/x).
#define S2 264
__global__ __launch_bounds__(256, 2) void k_gemm2(const float* __restrict__ x,
                                                  const float* __restrict__ b_out,
                                                  float* __restrict__ out) {
    extern __shared__ __nv_bfloat16 sm2[];
    __nv_bfloat16* As = sm2;              // [64 m][S2]   V tile
    __nv_bfloat16* Ws = sm2 + 64 * S2;    // [128 c][S2]  w_out
    int b = blockIdx.z;
    size_t m0 = (size_t)blockIdx.x * 64;
    int tid = threadIdx.x;

    const uint4* vsrc = (const uint4*)(g_V + ((size_t)b * MDIM + m0) * HDIM);
    for (int i = tid; i < 64 * 32; i += 256) {
        int m = i >> 5, q = i & 31;
        *((uint4*)(As + m * S2) + q) = vsrc[m * 32 + q];
    }
    const uint4* wsrc = (const uint4*)g_W2;
    for (int i = tid; i < 128 * 32; i += 256) {
        int c = i >> 5, q = i & 31;
        *((uint4*)(Ws + c * S2) + q) = wsrc[c * 32 + q];
    }
    __syncthreads();

    int wid = tid >> 5, lane = tid & 31;
    int wm = wid & 3, wn = wid >> 2;       // c-block wm*32, m-block wn*32
    int gid = lane >> 2, tg = lane & 3;

    unsigned aB[2], bB[2];
    {
        int arow = (lane & 15), akoff = (lane >> 4) * 8;
#pragma unroll
        for (int mt = 0; mt < 2; mt++)
            aB[mt] = sptr(Ws + (wm * 32 + mt * 16 + arow) * S2 + akoff);
        int brow = ((lane >> 4) << 3) + (lane & 7), bkoff = ((lane >> 3) & 1) * 8;
#pragma unroll
        for (int p = 0; p < 2; p++)
            bB[p] = sptr(As + (wn * 32 + p * 16 + brow) * S2 + bkoff);
    }

    float acc[2][4][4];
#pragma unroll
    for (int i = 0; i < 2; i++)
#pragma unroll
        for (int j = 0; j < 4; j++)
#pragma unroll
            for (int r = 0; r < 4; r++) acc[i][j][r] = 0.f;

#pragma unroll 4
    for (int kk = 0; kk < 256; kk += 16) {
        unsigned afr[2][4], bfr[2][4];
        ldsm4(aB[0] + kk * 2, afr[0]);
        ldsm4(aB[1] + kk * 2, afr[1]);
        ldsm4(bB[0] + kk * 2, bfr[0]);
        ldsm4(bB[1] + kk * 2, bfr[1]);
#pragma unroll
        for (int nt = 0; nt < 4; nt++) {
            const unsigned* bb = &bfr[nt >> 1][(nt & 1) * 2];
#pragma unroll
            for (int mt = 0; mt < 2; mt++) mma16816(acc[mt][nt], afr[mt], bb);
        }
    }

    // epilogue: out[b][c][m] = x + acc + b_out[c]; m contiguous per lane quad.
#pragma unroll
    for (int mt = 0; mt < 2; mt++) {
#pragma unroll
        for (int nt = 0; nt < 4; nt++) {
            int ml = wn * 32 + nt * 8 + tg * 2;
#pragma unroll
            for (int r = 0; r < 2; r++) {
                int c = wm * 32 + mt * 16 + gid + r * 8;
                float bo = b_out[c];
                size_t idx = ((size_t)(b * CDIM + c)) * MDIM + m0 + ml;
                float2 xr = *(const float2*)(x + idx);
                float2 o;
                o.x = xr.x + acc[mt][nt][r * 2 + 0] + bo;
                o.y = xr.y + acc[mt][nt][r * 2 + 1] + bo;
                *(float2*)(out + idx) = o;
            }
        }
    }
}

// ---------------- launch ------------------------------------------------------
extern "C" void kernel_launch(void* const* d_in, const int* in_sizes, int n_in,
                              void* d_out, int out_size) {
    const float* x      = (const float*)d_in[0];
    const float* g_norm = (const float*)d_in[1];
    const float* w_in   = (const float*)d_in[2];
    const float* b_in   = (const float*)d_in[3];
    const float* w_dw   = (const float*)d_in[4];
    const float* b_dw   = (const float*)d_in[5];
    const float* w_out  = (const float*)d_in[6];
    const float* b_out  = (const float*)d_in[7];
    float* out = (float*)d_out;

    const int smem1 = 384 * S1 * (int)sizeof(__nv_bfloat16);   // 104448
    const int smemd = DWSM * (int)sizeof(__nv_bfloat16);       // 52224
    const int smem2 = 192 * S2 * (int)sizeof(__nv_bfloat16);   // 101376
    cudaFuncSetAttribute(k_gemm1, cudaFuncAttributeMaxDynamicSharedMemorySize, smem1);
    cudaFuncSetAttribute(k_dw,    cudaFuncAttributeMaxDynamicSharedMemorySize, smemd);
    cudaFuncSetAttribute(k_gemm2, cudaFuncAttributeMaxDynamicSharedMemorySize, smem2);

    k_prep<<<256, 256>>>(w_in, g_norm, w_out);
    k_rms<<<dim3(TDIM / 64, FDIM, BATCH), 256>>>(x, g_norm);
    k_gemm1<<<dim3(MDIM / 128, HDIM / 128, BATCH), 512, smem1>>>(b_in);
    k_dw<<<dim3(TDIM / DWC, FDIM, BATCH), 256, smemd>>>(w_dw, b_dw);
    k_gemm2<<<dim3(MDIM / 64, 1, BATCH), 256, smem2>>>(x, b_out, out);
}